// round 2
// baseline (speedup 1.0000x reference)
#include <cuda_runtime.h>
#include <math.h>

// Problem constants
#define BB   8
#define NN   20000
#define PP   256
#define SS   32
#define CC   256
#define NCC  18
#define BP   (BB*PP)      // 2048

// ---------------- scratch (__device__ globals; no allocation allowed) ---------------
__device__ int   g_sel[BP*SS];
__device__ float g_nf [BP*128];
__device__ float g_lf [BP*256];
__device__ float g_ss [BB*256];
__device__ float g_ss2[BB*512];

// transposed weights: layout [K][O] (wt[c*O + o]) -- only point/label MLP weights
__device__ __align__(16) float g_mw0t [259*128];
__device__ __align__(16) float g_mw1t [128*128];
__device__ __align__(16) float g_mw2t [128*128];
__device__ __align__(16) float g_lw0t [146*256];
__device__ __align__(16) float g_lw1t [256*256];
__device__ __align__(16) float g_lw2t [256*256];

// ---------------- kernel T: fused tiled transpose of the 6 MLP weights --------------
// tile counts: mw0 36 | mw1 16 | mw2 16 | lw0 40 | lw1 64 | lw2 64  => 236 blocks
__global__ void k_transpose_all(const float* __restrict__ mw0, const float* __restrict__ mw1,
                                const float* __restrict__ mw2, const float* __restrict__ lw0,
                                const float* __restrict__ lw1, const float* __restrict__ lw2) {
    int t = blockIdx.x;
    const float* src; float* dst; int O, K, base;
    if      (t < 36)  { src = mw0; dst = g_mw0t; O = 128; K = 259; base = 0;   }
    else if (t < 52)  { src = mw1; dst = g_mw1t; O = 128; K = 128; base = 36;  }
    else if (t < 68)  { src = mw2; dst = g_mw2t; O = 128; K = 128; base = 52;  }
    else if (t < 108) { src = lw0; dst = g_lw0t; O = 256; K = 146; base = 68;  }
    else if (t < 172) { src = lw1; dst = g_lw1t; O = 256; K = 256; base = 108; }
    else              { src = lw2; dst = g_lw2t; O = 256; K = 256; base = 172; }
    int tile = t - base;
    int ntk = (K + 31) >> 5;
    int kt = tile % ntk, ot = tile / ntk;
    __shared__ float s[32][33];
    int k0 = kt * 32, o0 = ot * 32;
    int tx = threadIdx.x, ty = threadIdx.y;   // 32 x 8
    #pragma unroll
    for (int i = ty; i < 32; i += 8) {
        int o = o0 + i, k = k0 + tx;
        if (o < O && k < K) s[i][tx] = src[o * K + k];
    }
    __syncthreads();
    #pragma unroll
    for (int i = ty; i < 32; i += 8) {
        int k = k0 + i, o = o0 + tx;
        if (k < K && o < O) dst[k * O + o] = s[tx][i];
    }
}

// ---------------- kernel A: in-box sampling (warp per proposal, early exit) ---------
__global__ void k_sample(const float* __restrict__ xyz,
                         const float* __restrict__ bsize,
                         const int*   __restrict__ inds) {
    __shared__ int buf[8][SS];
    int lane = threadIdx.x & 31, w = threadIdx.x >> 5;
    int q = blockIdx.x * 8 + w;
    int b = q >> 8;
    int n0 = inds[q];
    const float* xb = xyz + (size_t)b * NN * 3;
    float cx = xb[n0*3+0], cy = xb[n0*3+1], cz = xb[n0*3+2];
    float hx = bsize[q*3+0]*0.5f, hy = bsize[q*3+1]*0.5f, hz = bsize[q*3+2]*0.5f;

    int found = 0;
    for (int base = 0; base < NN; base += 32) {   // NN = 625*32 exactly
        int n = base + lane;
        float px = xb[n*3+0], py = xb[n*3+1], pz = xb[n*3+2];
        bool in = (fabsf(px-cx) <= hx) && (fabsf(py-cy) <= hy) && (fabsf(pz-cz) <= hz);
        unsigned m = __ballot_sync(0xffffffffu, in);
        if (in) {
            int slot = found + __popc(m & ((1u << lane) - 1u));
            if (slot < SS) buf[w][slot] = n;
        }
        found += __popc(m);
        if (found >= SS) break;                    // warp-uniform
    }
    __syncwarp();
    int eff = found < SS ? found : SS;
    int sel = 0;
    if (eff > 0) sel = buf[w][lane % eff];        // cycle first-eff in order (matches argsort)
    g_sel[q*SS + lane] = sel;
}

// ---------------- kernel E: time MLPs, warp-dot on RAW weights ----------------------
__device__ __forceinline__ float gelu_exact(float x) {
    return 0.5f * x * (1.0f + erff(x * 0.70710678118654752f));
}
__device__ __forceinline__ float silu_f(float x) { return x / (1.0f + expf(-x)); }

__device__ __forceinline__ float warp_dot(const float* __restrict__ w,
                                          const float* __restrict__ in, int K, int lane) {
    float a = 0.0f;
    #pragma unroll 4
    for (int c = lane; c < K; c += 32) a += w[c] * in[c];
    a += __shfl_xor_sync(0xffffffffu, a, 16);
    a += __shfl_xor_sync(0xffffffffu, a, 8);
    a += __shfl_xor_sync(0xffffffffu, a, 4);
    a += __shfl_xor_sync(0xffffffffu, a, 2);
    a += __shfl_xor_sync(0xffffffffu, a, 1);
    return a;
}

__global__ void k_time(const float* __restrict__ ts,
                       const float* __restrict__ tw0, const float* __restrict__ tb0,
                       const float* __restrict__ tw1, const float* __restrict__ tb1,
                       const float* __restrict__ bw,  const float* __restrict__ bb_,
                       const float* __restrict__ tlw0, const float* __restrict__ tlb0,
                       const float* __restrict__ tlw1, const float* __restrict__ tlb1,
                       const float* __restrict__ blw,  const float* __restrict__ blb) {
    __shared__ float e1[128], e2[256], t1[512], s1[512], t2[1024], s2[1024];
    int b = blockIdx.x, tid = threadIdx.x;           // 1024 threads
    int lane = tid & 31, warp = tid >> 5;            // 32 warps
    float t = ts[b];
    if (tid < 64)  { float f = expf(tid * (-9.210340371976184f/63.0f));
                     float e = t*f; e1[tid] = sinf(e); e1[64+tid]  = cosf(e); }
    if (tid < 128) { float f = expf(tid * (-9.210340371976184f/127.0f));
                     float e = t*f; e2[tid] = sinf(e); e2[128+tid] = cosf(e); }
    __syncthreads();
    for (int r = warp; r < 512; r += 32) {
        float a = warp_dot(tw0 + r*128, e1, 128, lane) + tb0[r];
        if (lane == 0) t1[r] = gelu_exact(a);
    }
    for (int r = warp; r < 1024; r += 32) {
        float a = warp_dot(tlw0 + r*256, e2, 256, lane) + tlb0[r];
        if (lane == 0) t2[r] = gelu_exact(a);
    }
    __syncthreads();
    for (int r = warp; r < 512; r += 32) {
        float a = warp_dot(tw1 + r*512, t1, 512, lane) + tb1[r];
        if (lane == 0) s1[r] = silu_f(a);
    }
    for (int r = warp; r < 1024; r += 32) {
        float a = warp_dot(tlw1 + (size_t)r*1024, t2, 1024, lane) + tlb1[r];
        if (lane == 0) s2[r] = silu_f(a);
    }
    __syncthreads();
    for (int r = warp; r < 256; r += 32) {
        float a = warp_dot(bw + r*512, s1, 512, lane) + bb_[r];
        if (lane == 0) g_ss[b*256 + r] = a;
    }
    for (int r = warp; r < 512; r += 32) {
        float a = warp_dot(blw + (size_t)r*1024, s2, 1024, lane) + blb[r];
        if (lane == 0) g_ss2[b*512 + r] = a;
    }
}

// ---------------- kernel B: gather + point MLP + maxpool + label MLP ----------------
#define GST 263   // 263 % 32 = 7 -> conflict-free
#define HST 133   // 133 % 32 = 5 -> conflict-free

// 2 points x 16 outputs per thread; og in [0,8), sp in [0,16)
template<int K>
__device__ __forceinline__ void layer2p(const float* __restrict__ in, int istride,
                                        const float* __restrict__ wt,
                                        const float* __restrict__ bias,
                                        float* __restrict__ out, int ostride,
                                        int sp, int og) {
    float a0[16], a1[16];
    {
        const float4* b4 = reinterpret_cast<const float4*>(bias) + og * 4;
        float4 t0 = b4[0], t1 = b4[1], t2 = b4[2], t3 = b4[3];
        a0[0]=t0.x; a0[1]=t0.y; a0[2]=t0.z; a0[3]=t0.w;
        a0[4]=t1.x; a0[5]=t1.y; a0[6]=t1.z; a0[7]=t1.w;
        a0[8]=t2.x; a0[9]=t2.y; a0[10]=t2.z; a0[11]=t2.w;
        a0[12]=t3.x; a0[13]=t3.y; a0[14]=t3.z; a0[15]=t3.w;
        #pragma unroll
        for (int j = 0; j < 16; j++) a1[j] = a0[j];
    }
    const float4* w4 = reinterpret_cast<const float4*>(wt) + og * 4;
    const float* i0 = in + sp * istride;
    const float* i1 = in + (sp + 16) * istride;
    #pragma unroll 2
    for (int c = 0; c < K; c++) {
        float x = i0[c], y = i1[c];
        float4 w0 = w4[c*32+0], w1 = w4[c*32+1], w2 = w4[c*32+2], w3 = w4[c*32+3];
        a0[0]  += x*w0.x; a0[1]  += x*w0.y; a0[2]  += x*w0.z; a0[3]  += x*w0.w;
        a0[4]  += x*w1.x; a0[5]  += x*w1.y; a0[6]  += x*w1.z; a0[7]  += x*w1.w;
        a0[8]  += x*w2.x; a0[9]  += x*w2.y; a0[10] += x*w2.z; a0[11] += x*w2.w;
        a0[12] += x*w3.x; a0[13] += x*w3.y; a0[14] += x*w3.z; a0[15] += x*w3.w;
        a1[0]  += y*w0.x; a1[1]  += y*w0.y; a1[2]  += y*w0.z; a1[3]  += y*w0.w;
        a1[4]  += y*w1.x; a1[5]  += y*w1.y; a1[6]  += y*w1.z; a1[7]  += y*w1.w;
        a1[8]  += y*w2.x; a1[9]  += y*w2.y; a1[10] += y*w2.z; a1[11] += y*w2.w;
        a1[12] += y*w3.x; a1[13] += y*w3.y; a1[14] += y*w3.z; a1[15] += y*w3.w;
    }
    float* o0 = out + sp * ostride + og * 16;
    float* o1 = out + (sp + 16) * ostride + og * 16;
    #pragma unroll
    for (int j = 0; j < 16; j++) o0[j] = fmaxf(a0[j], 0.0f);
    #pragma unroll
    for (int j = 0; j < 16; j++) o1[j] = fmaxf(a1[j], 0.0f);
}

// label sub-layer: 128 threads, 2 consecutive outputs per thread, float2 weight loads
__device__ __forceinline__ void label_layer(const float* __restrict__ in, int K,
                                            const float* __restrict__ wt,  // [K][256]
                                            const float* __restrict__ bias,
                                            float* __restrict__ out, int tid) {
    float2 acc = reinterpret_cast<const float2*>(bias)[tid];
    #pragma unroll 4
    for (int c = 0; c < K; c++) {
        float v = in[c];
        float2 w = reinterpret_cast<const float2*>(wt + c*256)[tid];
        acc.x += v * w.x; acc.y += v * w.y;
    }
    out[2*tid]   = fmaxf(acc.x, 0.0f);
    out[2*tid+1] = fmaxf(acc.y, 0.0f);
}

__global__ void k_mlp(const float* __restrict__ xyz, const float* __restrict__ feat,
                      const int* __restrict__ inds,
                      const float* __restrict__ mb0, const float* __restrict__ mb1,
                      const float* __restrict__ mb2,
                      const float* __restrict__ blabel,
                      const float* __restrict__ lb0, const float* __restrict__ lb1,
                      const float* __restrict__ lb2) {
    extern __shared__ float sm[];
    float* g  = sm;                    // [32][263]  (also reused as hB)
    float* hA = sm + 32 * GST;         // [32][133]
    __shared__ int   sidx[SS];
    __shared__ float ctr[3];
    __shared__ float in0[148];
    __shared__ float hL1[256], hL2[256];

    int q = blockIdx.x, b = q >> 8;
    int tid = threadIdx.x;             // 128 threads
    if (tid < SS) sidx[tid] = g_sel[q*SS + tid];
    if (tid < 3) {
        int n0 = inds[q];
        ctr[tid] = xyz[((size_t)b*NN + n0)*3 + tid];
    }
    if (tid < NCC) in0[tid] = blabel[q*NCC + tid];
    __syncthreads();

    const float* fb = feat + (size_t)b * CC * NN;
    for (int i = tid; i < SS * CC; i += 128) {
        int s = i >> 8, c = i & 255;
        g[s*GST + 3 + c] = __ldg(fb + (size_t)c * NN + sidx[s]);
    }
    if (tid < SS * 3) {
        int s = tid / 3, d = tid - s * 3;
        g[s*GST + d] = xyz[((size_t)b*NN + sidx[s])*3 + d] - ctr[d];
    }
    __syncthreads();

    int sp = tid & 15, og = tid >> 4;
    layer2p<259>(g,  GST, g_mw0t, mb0, hA, HST, sp, og); __syncthreads();
    layer2p<128>(hA, HST, g_mw1t, mb1, g,  HST, sp, og); __syncthreads();
    layer2p<128>(g,  HST, g_mw2t, mb2, hA, HST, sp, og); __syncthreads();

    // maxpool over 32 samples -> nf[128] (relu outputs >= 0)
    {
        float m = 0.0f;
        #pragma unroll
        for (int s2 = 0; s2 < SS; s2++) m = fmaxf(m, hA[s2*HST + tid]);
        g_nf[q*128 + tid] = m;
        in0[NCC + tid] = m;
    }
    __syncthreads();

    // fused label MLP: 146 -> 256 -> 256 -> 256
    label_layer(in0, 146, g_lw0t, lb0, hL1, tid); __syncthreads();
    label_layer(hL1, 256, g_lw1t, lb1, hL2, tid); __syncthreads();
    {
        float2 acc = reinterpret_cast<const float2*>(lb2)[tid];
        #pragma unroll 4
        for (int c = 0; c < 256; c++) {
            float v = hL2[c];
            float2 w = reinterpret_cast<const float2*>(g_lw2t + c*256)[tid];
            acc.x += v * w.x; acc.y += v * w.y;
        }
        g_lf[q*256 + 2*tid]   = fmaxf(acc.x, 0.0f);
        g_lf[q*256 + 2*tid+1] = fmaxf(acc.y, 0.0f);
    }
}

// ---------------- kernel D: FiLM + all outputs ---------------------------------------
// FiLM index collapse (verified): scale index d' = (d*P + p) mod D
//   D=128, P=256 -> d' = p % 128 ;  D=256, P=256 -> d' = p
__global__ void k_out(float* __restrict__ out, const float* __restrict__ xyz,
                      const int* __restrict__ inds) {
    const int O0 = BB*PP*3;           // 6144
    const int O1 = O0 + BB*128*PP;    // 268288
    const int O2 = O1 + BB*256*PP;    // 792576
    const int O3 = O2 + BB*PP;        // 794624
    int i = blockIdx.x * blockDim.x + threadIdx.x;
    if (i < O0) {
        int b = i / (PP*3); int r = i - b*(PP*3); int p = r/3, d = r - p*3;
        out[i] = xyz[((size_t)b*NN + inds[b*PP + p])*3 + d];
    } else if (i < O1) {
        int j = i - O0;
        int b = j >> 15;
        int r = j & 32767;
        int d = r >> 8, p = r & 255;
        int m = p & 127;
        out[i] = g_nf[((b<<8) + p)*128 + d] * (g_ss[b*256 + m] + 1.0f)
               + g_ss[b*256 + 128 + m];
    } else if (i < O2) {
        int j = i - O1;
        int b = j >> 16;
        int r = j & 65535;
        int d = r >> 8, p = r & 255;
        out[i] = g_lf[((b<<8) + p)*256 + d] * (g_ss2[b*512 + p] + 1.0f)
               + g_ss2[b*512 + 256 + p];
    } else if (i < O3) {
        out[i] = (float)inds[i - O2];
    }
}

// ---------------- launcher -----------------------------------------------------------
extern "C" void kernel_launch(void* const* d_in, const int* in_sizes, int n_in,
                              void* d_out, int out_size) {
    const float* xyz    = (const float*)d_in[0];
    const float* feat   = (const float*)d_in[1];
    const float* bsize  = (const float*)d_in[2];
    const float* blabel = (const float*)d_in[3];
    const float* ts     = (const float*)d_in[4];
    const int*   inds   = (const int*)  d_in[5];
    const float* mw0 = (const float*)d_in[6],  *mb0 = (const float*)d_in[7];
    const float* mw1 = (const float*)d_in[8],  *mb1 = (const float*)d_in[9];
    const float* mw2 = (const float*)d_in[10], *mb2 = (const float*)d_in[11];
    const float* lw0 = (const float*)d_in[12], *lb0 = (const float*)d_in[13];
    const float* lw1 = (const float*)d_in[14], *lb1 = (const float*)d_in[15];
    const float* lw2 = (const float*)d_in[16], *lb2 = (const float*)d_in[17];
    const float* tw0 = (const float*)d_in[18], *tb0 = (const float*)d_in[19];
    const float* tw1 = (const float*)d_in[20], *tb1 = (const float*)d_in[21];
    const float* bw  = (const float*)d_in[22], *bbv = (const float*)d_in[23];
    const float* tlw0= (const float*)d_in[24], *tlb0= (const float*)d_in[25];
    const float* tlw1= (const float*)d_in[26], *tlb1= (const float*)d_in[27];
    const float* blw = (const float*)d_in[28], *blb = (const float*)d_in[29];
    float* out = (float*)d_out;

    dim3 tb(32, 8);
    k_transpose_all<<<236, tb>>>(mw0, mw1, mw2, lw0, lw1, lw2);     // launch 0
    k_sample<<<BP/8, 256>>>(xyz, bsize, inds);                      // launch 1
    k_time<<<BB, 1024>>>(ts, tw0, tb0, tw1, tb1, bw, bbv,
                         tlw0, tlb0, tlw1, tlb1, blw, blb);         // launch 2

    int smem_b = (32*GST + 32*HST) * (int)sizeof(float);            // 50688 B
    cudaFuncSetAttribute(k_mlp, cudaFuncAttributeMaxDynamicSharedMemorySize, smem_b);
    k_mlp<<<BP, 128, smem_b>>>(xyz, feat, inds, mb0, mb1, mb2,
                               blabel, lb0, lb1, lb2);              // launch 3

    const int total = BB*PP*3 + BB*128*PP + BB*256*PP + BB*PP;      // 794624
    k_out<<<(total + 255)/256, 256>>>(out, xyz, inds);              // launch 4
}

// round 4
// speedup vs baseline: 1.2311x; 1.2311x over previous
#include <cuda_runtime.h>
#include <math.h>

// Problem constants
#define BB   8
#define NN   20000
#define NPAD 20096        // 157 * 128
#define PP   256
#define SS   32
#define CC   256
#define NCC  18
#define BP   (BB*PP)      // 2048

// ---------------- scratch (__device__ globals; no allocation allowed) ---------------
// NOTE: never pass these as kernel arguments from host code -- host-side symbol
// addresses are NOT device addresses (ATS makes the bug silent on GB300).
__device__ int   g_sel[BP*SS];
__device__ float g_nf [BP*128];
__device__ float g_lf [BP*256];
__device__ float g_ss [BB*256];
__device__ float g_ss2[BB*512];
__device__ __align__(16) float g_sx[BB*NPAD];
__device__ __align__(16) float g_sy[BB*NPAD];
__device__ __align__(16) float g_sz[BB*NPAD];
__device__ float g_e1[BB*128], g_e2[BB*256];
__device__ float g_t1[BB*512], g_t2[BB*1024];
__device__ float g_s1[BB*512], g_s2[BB*1024];

// transposed weights: layout [K][O] (wt[c*O + o]) -- point/label MLP weights only
__device__ __align__(16) float g_mw0t [259*128];
__device__ __align__(16) float g_mw1t [128*128];
__device__ __align__(16) float g_mw2t [128*128];
__device__ __align__(16) float g_lw0t [146*256];
__device__ __align__(16) float g_lw1t [256*256];
__device__ __align__(16) float g_lw2t [256*256];

// ---------------- activations --------------------------------------------------------
__device__ __forceinline__ float gelu_exact(float x) {
    return 0.5f * x * (1.0f + erff(x * 0.70710678118654752f));
}
__device__ __forceinline__ float silu_f(float x) { return x / (1.0f + expf(-x)); }

// ---------------- kernel T: fused tiled transpose of the 6 MLP weights --------------
__global__ void k_transpose_all(const float* __restrict__ mw0, const float* __restrict__ mw1,
                                const float* __restrict__ mw2, const float* __restrict__ lw0,
                                const float* __restrict__ lw1, const float* __restrict__ lw2) {
    int t = blockIdx.x;
    const float* src; float* dst; int O, K, base;
    if      (t < 36)  { src = mw0; dst = g_mw0t; O = 128; K = 259; base = 0;   }
    else if (t < 52)  { src = mw1; dst = g_mw1t; O = 128; K = 128; base = 36;  }
    else if (t < 68)  { src = mw2; dst = g_mw2t; O = 128; K = 128; base = 52;  }
    else if (t < 108) { src = lw0; dst = g_lw0t; O = 256; K = 146; base = 68;  }
    else if (t < 172) { src = lw1; dst = g_lw1t; O = 256; K = 256; base = 108; }
    else              { src = lw2; dst = g_lw2t; O = 256; K = 256; base = 172; }
    int tile = t - base;
    int ntk = (K + 31) >> 5;
    int kt = tile % ntk, ot = tile / ntk;
    __shared__ float s[32][33];
    int k0 = kt * 32, o0 = ot * 32;
    int tx = threadIdx.x, ty = threadIdx.y;   // 32 x 8
    #pragma unroll
    for (int i = ty; i < 32; i += 8) {
        int o = o0 + i, k = k0 + tx;
        if (o < O && k < K) s[i][tx] = src[o * K + k];
    }
    __syncthreads();
    #pragma unroll
    for (int i = ty; i < 32; i += 8) {
        int k = k0 + i, o = o0 + tx;
        if (k < K && o < O) dst[k * O + o] = s[tx][i];
    }
}

// ---------------- kernel S0: AoS -> SoA with sentinel padding ------------------------
__global__ void k_soa(const float* __restrict__ xyz) {
    int i = blockIdx.x * 256 + threadIdx.x;
    if (i >= BB * NPAD) return;
    int b = i / NPAD, n = i - b * NPAD;
    float x = 3e38f, y = 3e38f, z = 3e38f;
    if (n < NN) {
        const float* p = xyz + ((size_t)b * NN + n) * 3;
        x = p[0]; y = p[1]; z = p[2];
    }
    g_sx[i] = x; g_sy[i] = y; g_sz[i] = z;
}

// ---------------- kernel A: in-box sampling (warp/proposal, float4, early exit) -----
__global__ void k_sample(const float* __restrict__ xyz,
                         const float* __restrict__ bsize,
                         const int*   __restrict__ inds) {
    __shared__ int buf[8][SS];
    int lane = threadIdx.x & 31, w = threadIdx.x >> 5;
    int q = blockIdx.x * 8 + w;
    int b = q >> 8;
    int n0 = inds[q];
    const float* cp = xyz + ((size_t)b * NN + n0) * 3;
    float cx = cp[0], cy = cp[1], cz = cp[2];
    float hx = bsize[q*3+0]*0.5f, hy = bsize[q*3+1]*0.5f, hz = bsize[q*3+2]*0.5f;
    const float4* X = (const float4*)(g_sx + b * NPAD);
    const float4* Y = (const float4*)(g_sy + b * NPAD);
    const float4* Z = (const float4*)(g_sz + b * NPAD);

    unsigned below = (1u << lane) - 1u;
    int found = 0;
    for (int it = 0; it < NPAD/128; it++) {        // 157 iters
        int v = it * 32 + lane;
        float4 xs = X[v], ys = Y[v], zs = Z[v];
        bool i0 = (fabsf(xs.x-cx)<=hx) && (fabsf(ys.x-cy)<=hy) && (fabsf(zs.x-cz)<=hz);
        bool i1 = (fabsf(xs.y-cx)<=hx) && (fabsf(ys.y-cy)<=hy) && (fabsf(zs.y-cz)<=hz);
        bool i2 = (fabsf(xs.z-cx)<=hx) && (fabsf(ys.z-cy)<=hy) && (fabsf(zs.z-cz)<=hz);
        bool i3 = (fabsf(xs.w-cx)<=hx) && (fabsf(ys.w-cy)<=hy) && (fabsf(zs.w-cz)<=hz);
        unsigned m0 = __ballot_sync(0xffffffffu, i0);
        unsigned m1 = __ballot_sync(0xffffffffu, i1);
        unsigned m2 = __ballot_sync(0xffffffffu, i2);
        unsigned m3 = __ballot_sync(0xffffffffu, i3);
        if (m0 | m1 | m2 | m3) {
            int pre = found
                    + __popc(m0 & below) + __popc(m1 & below)
                    + __popc(m2 & below) + __popc(m3 & below);
            int np = it * 128 + 4 * lane;
            unsigned b0 = (m0 >> lane) & 1u, b1 = (m1 >> lane) & 1u, b2 = (m2 >> lane) & 1u;
            if (i0 && pre < SS)                    buf[w][pre] = np;
            int r1 = pre + (int)b0;
            if (i1 && r1 < SS)                     buf[w][r1] = np + 1;
            int r2 = r1 + (int)b1;
            if (i2 && r2 < SS)                     buf[w][r2] = np + 2;
            int r3 = r2 + (int)b2;
            if (i3 && r3 < SS)                     buf[w][r3] = np + 3;
        }
        found += __popc(m0) + __popc(m1) + __popc(m2) + __popc(m3);
        if (found >= SS) break;                    // warp-uniform
    }
    __syncwarp();
    int eff = found < SS ? found : SS;
    int sel = 0;
    if (eff > 0) sel = buf[w][lane % eff];
    g_sel[q*SS + lane] = sel;
}

// ---------------- time-MLP chain: embeddings + 3 GEMV stage kernels -----------------
__global__ void k_emb(const float* __restrict__ ts) {  // grid BB, block 128
    int b = blockIdx.x, tid = threadIdx.x;
    float t = ts[b];
    if (tid < 64) {
        float f = expf(tid * (-9.210340371976184f/63.0f));
        float e = t * f;
        g_e1[b*128 + tid] = sinf(e); g_e1[b*128 + 64 + tid] = cosf(e);
    }
    {
        float f = expf(tid * (-9.210340371976184f/127.0f));
        float e = t * f;
        g_e2[b*256 + tid] = sinf(e); g_e2[b*256 + 128 + tid] = cosf(e);
    }
}

// One block = 32 rows x 8 batches. Weights staged in smem, read once from L2/DRAM.
// Scratch in/out pointers resolved IN DEVICE CODE from `stage` (0,1,2) + side.
__global__ void k_tstage(const float* __restrict__ WA, const float* __restrict__ bA,
                         const float* __restrict__ WB, const float* __restrict__ bB,
                         int RA, int stage) {
    extern __shared__ float dsm[];
    int blk = blockIdx.x;
    int nA = RA >> 5;
    bool isA = blk < nA;
    const float *W = isA ? WA : WB;
    const float *bias = isA ? bA : bB;
    int row0 = (isA ? blk : blk - nA) << 5;
    const float* gin; float* gout; int K, R; int act;
    if (stage == 0) {
        act = 0;
        if (isA) { gin = g_e1; gout = g_t1; K = 128;  R = 512;  }
        else     { gin = g_e2; gout = g_t2; K = 256;  R = 1024; }
    } else if (stage == 1) {
        act = 1;
        if (isA) { gin = g_t1; gout = g_s1; K = 512;  R = 512;  }
        else     { gin = g_t2; gout = g_s2; K = 1024; R = 1024; }
    } else {
        act = 2;
        if (isA) { gin = g_s1; gout = g_ss;  K = 512;  R = 256; }
        else     { gin = g_s2; gout = g_ss2; K = 1024; R = 512; }
    }
    float* in_s = dsm;                 // [8][K+4]
    float* w_s  = dsm + 8 * (K + 4);   // [32][132]
    int tid = threadIdx.x;             // 256
    int rl = tid >> 3, bb = tid & 7;
    int stride = K + 4;
    int ksh = __ffs(K) - 1;            // K is a power of two (128..1024)
    for (int i = tid; i < (K << 3); i += 256) {
        int b2 = i >> ksh, c = i & (K - 1);
        in_s[b2 * stride + c] = gin[i];
    }
    float acc = 0.0f;
    for (int ko = 0; ko < K; ko += 128) {
        __syncthreads();
        #pragma unroll
        for (int i = tid; i < 1024; i += 256) {      // 32 rows x 128 cols as float4
            int r = i >> 5, c4 = i & 31;
            float4 v = *(const float4*)(W + (size_t)(row0 + r) * K + ko + c4 * 4);
            *(float4*)&w_s[r * 132 + c4 * 4] = v;
        }
        __syncthreads();
        const float* wr = w_s + rl * 132;
        const float* ir = in_s + bb * stride + ko;
        #pragma unroll 8
        for (int c = 0; c < 128; c++) acc += wr[c] * ir[c];
    }
    acc += bias[row0 + rl];
    if (act == 0) acc = gelu_exact(acc);
    else if (act == 1) acc = silu_f(acc);
    gout[bb * R + row0 + rl] = acc;
}

// ---------------- kernel B: gather + point MLP + maxpool + label MLP ----------------
#define GST 263   // 263 % 32 = 7 -> conflict-free
#define HST 133   // 133 % 32 = 5 -> conflict-free

// 1 point x 16 outputs per thread; 256 threads = 32 points x 8 output groups.
// Weight loads are warp-uniform (og constant per warp) -> single-sector broadcasts.
template<int K>
__device__ __forceinline__ void layer16(const float* __restrict__ in, int istride,
                                        const float* __restrict__ wt,
                                        const float* __restrict__ bias,
                                        float* __restrict__ out,
                                        int sp, int og) {
    float a0[16];
    {
        const float4* b4 = reinterpret_cast<const float4*>(bias) + og * 4;
        float4 t0 = b4[0], t1 = b4[1], t2 = b4[2], t3 = b4[3];
        a0[0]=t0.x; a0[1]=t0.y; a0[2]=t0.z; a0[3]=t0.w;
        a0[4]=t1.x; a0[5]=t1.y; a0[6]=t1.z; a0[7]=t1.w;
        a0[8]=t2.x; a0[9]=t2.y; a0[10]=t2.z; a0[11]=t2.w;
        a0[12]=t3.x; a0[13]=t3.y; a0[14]=t3.z; a0[15]=t3.w;
    }
    const float4* w4 = reinterpret_cast<const float4*>(wt) + og * 4;
    const float* inr = in + sp * istride;
    #pragma unroll 2
    for (int c = 0; c < K; c++) {
        float x = inr[c];
        float4 w0 = w4[c*32+0], w1 = w4[c*32+1], w2 = w4[c*32+2], w3 = w4[c*32+3];
        a0[0]  += x*w0.x; a0[1]  += x*w0.y; a0[2]  += x*w0.z; a0[3]  += x*w0.w;
        a0[4]  += x*w1.x; a0[5]  += x*w1.y; a0[6]  += x*w1.z; a0[7]  += x*w1.w;
        a0[8]  += x*w2.x; a0[9]  += x*w2.y; a0[10] += x*w2.z; a0[11] += x*w2.w;
        a0[12] += x*w3.x; a0[13] += x*w3.y; a0[14] += x*w3.z; a0[15] += x*w3.w;
    }
    float* o = out + sp * HST + og * 16;
    #pragma unroll
    for (int j = 0; j < 16; j++) o[j] = fmaxf(a0[j], 0.0f);
}

__global__ void __launch_bounds__(256) k_mlp(
                      const float* __restrict__ xyz, const float* __restrict__ feat,
                      const int* __restrict__ inds,
                      const float* __restrict__ mb0, const float* __restrict__ mb1,
                      const float* __restrict__ mb2,
                      const float* __restrict__ blabel,
                      const float* __restrict__ lb0, const float* __restrict__ lb1,
                      const float* __restrict__ lb2) {
    extern __shared__ float sm[];
    float* g  = sm;                    // [32][263]  (also reused as hB w/ stride HST)
    float* hA = sm + 32 * GST;         // [32][133]
    __shared__ int   sidx[SS];
    __shared__ float ctr[3];
    __shared__ float in0[148];
    __shared__ float hL1[256], hL2[256];

    int q = blockIdx.x, b = q >> 8;
    int tid = threadIdx.x;             // 256 threads
    if (tid < SS) sidx[tid] = g_sel[q*SS + tid];
    if (tid < 3) {
        int n0 = inds[q];
        ctr[tid] = xyz[((size_t)b*NN + n0)*3 + tid];
    }
    if (tid < NCC) in0[tid] = blabel[q*NCC + tid];
    __syncthreads();

    const float* fb = feat + (size_t)b * CC * NN;
    for (int i = tid; i < SS * CC; i += 256) {
        int s = i & 31, c = i >> 5;                // warp = 32 points, one channel
        g[s*GST + 3 + c] = __ldg(fb + (size_t)c * NN + sidx[s]);
    }
    if (tid < SS * 3) {
        int s = tid / 3, d = tid - s * 3;
        g[s*GST + d] = xyz[((size_t)b*NN + sidx[s])*3 + d] - ctr[d];
    }
    __syncthreads();

    int sp = tid & 31, og = tid >> 5;
    layer16<259>(g,  GST, g_mw0t, mb0, hA, sp, og); __syncthreads();
    layer16<128>(hA, HST, g_mw1t, mb1, g,  sp, og); __syncthreads();
    layer16<128>(g,  HST, g_mw2t, mb2, hA, sp, og); __syncthreads();

    // maxpool over 32 samples -> nf[128] (relu outputs >= 0)
    if (tid < 128) {
        float m = 0.0f;
        #pragma unroll
        for (int s2 = 0; s2 < SS; s2++) m = fmaxf(m, hA[s2*HST + tid]);
        g_nf[q*128 + tid] = m;
        in0[NCC + tid] = m;
    }
    __syncthreads();

    // fused label MLP: 146 -> 256 -> 256 -> 256 ; one output per thread
    {
        float acc = lb0[tid];
        #pragma unroll 2
        for (int c = 0; c < 146; c++) acc += in0[c] * g_lw0t[c*256 + tid];
        hL1[tid] = fmaxf(acc, 0.0f);
    }
    __syncthreads();
    {
        float acc = lb1[tid];
        #pragma unroll 4
        for (int c = 0; c < 256; c++) acc += hL1[c] * g_lw1t[c*256 + tid];
        hL2[tid] = fmaxf(acc, 0.0f);
    }
    __syncthreads();
    {
        float acc = lb2[tid];
        #pragma unroll 4
        for (int c = 0; c < 256; c++) acc += hL2[c] * g_lw2t[c*256 + tid];
        g_lf[q*256 + tid] = fmaxf(acc, 0.0f);
    }
}

// ---------------- kernel D: FiLM + all outputs ---------------------------------------
// FiLM index collapse (verified): scale index d' = (d*P + p) mod D
//   D=128, P=256 -> d' = p % 128 ;  D=256, P=256 -> d' = p
__global__ void k_out(float* __restrict__ out, const float* __restrict__ xyz,
                      const int* __restrict__ inds) {
    const int O0 = BB*PP*3;           // 6144
    const int O1 = O0 + BB*128*PP;    // 268288
    const int O2 = O1 + BB*256*PP;    // 792576
    const int O3 = O2 + BB*PP;        // 794624
    int i = blockIdx.x * blockDim.x + threadIdx.x;
    if (i < O0) {
        int b = i / (PP*3); int r = i - b*(PP*3); int p = r/3, d = r - p*3;
        out[i] = xyz[((size_t)b*NN + inds[b*PP + p])*3 + d];
    } else if (i < O1) {
        int j = i - O0;
        int b = j >> 15;
        int r = j & 32767;
        int d = r >> 8, p = r & 255;
        int m = p & 127;
        out[i] = g_nf[((b<<8) + p)*128 + d] * (g_ss[b*256 + m] + 1.0f)
               + g_ss[b*256 + 128 + m];
    } else if (i < O2) {
        int j = i - O1;
        int b = j >> 16;
        int r = j & 65535;
        int d = r >> 8, p = r & 255;
        out[i] = g_lf[((b<<8) + p)*256 + d] * (g_ss2[b*512 + p] + 1.0f)
               + g_ss2[b*512 + 256 + p];
    } else if (i < O3) {
        out[i] = (float)inds[i - O2];
    }
}

// ---------------- launcher -----------------------------------------------------------
extern "C" void kernel_launch(void* const* d_in, const int* in_sizes, int n_in,
                              void* d_out, int out_size) {
    const float* xyz    = (const float*)d_in[0];
    const float* feat   = (const float*)d_in[1];
    const float* bsize  = (const float*)d_in[2];
    const float* blabel = (const float*)d_in[3];
    const float* ts     = (const float*)d_in[4];
    const int*   inds   = (const int*)  d_in[5];
    const float* mw0 = (const float*)d_in[6],  *mb0 = (const float*)d_in[7];
    const float* mw1 = (const float*)d_in[8],  *mb1 = (const float*)d_in[9];
    const float* mw2 = (const float*)d_in[10], *mb2 = (const float*)d_in[11];
    const float* lw0 = (const float*)d_in[12], *lb0 = (const float*)d_in[13];
    const float* lw1 = (const float*)d_in[14], *lb1 = (const float*)d_in[15];
    const float* lw2 = (const float*)d_in[16], *lb2 = (const float*)d_in[17];
    const float* tw0 = (const float*)d_in[18], *tb0 = (const float*)d_in[19];
    const float* tw1 = (const float*)d_in[20], *tb1 = (const float*)d_in[21];
    const float* bw  = (const float*)d_in[22], *bbv = (const float*)d_in[23];
    const float* tlw0= (const float*)d_in[24], *tlb0= (const float*)d_in[25];
    const float* tlw1= (const float*)d_in[26], *tlb1= (const float*)d_in[27];
    const float* blw = (const float*)d_in[28], *blb = (const float*)d_in[29];
    float* out = (float*)d_out;

    dim3 tb(32, 8);
    k_transpose_all<<<236, tb>>>(mw0, mw1, mw2, lw0, lw1, lw2);
    k_soa<<<(BB*NPAD + 255)/256, 256>>>(xyz);
    k_emb<<<BB, 128>>>(ts);
    k_sample<<<BP/8, 256>>>(xyz, bsize, inds);

    int smem_t = (8*(1024+4) + 32*132) * (int)sizeof(float);   // 49792 B
    cudaFuncSetAttribute(k_tstage, cudaFuncAttributeMaxDynamicSharedMemorySize, smem_t);
    k_tstage<<<48, 256, smem_t>>>(tw0, tb0, tlw0, tlb0, 512, 0);

    int smem_b = (32*GST + 32*HST) * (int)sizeof(float);       // 50688 B
    cudaFuncSetAttribute(k_mlp, cudaFuncAttributeMaxDynamicSharedMemorySize, smem_b);
    k_mlp<<<BP, 256, smem_b>>>(xyz, feat, inds, mb0, mb1, mb2,
                               blabel, lb0, lb1, lb2);

    k_tstage<<<48, 256, smem_t>>>(tw1, tb1, tlw1, tlb1, 512, 1);
    k_tstage<<<24, 256, smem_t>>>(bw,  bbv, blw,  blb,  256, 2);

    const int total = BB*PP*3 + BB*128*PP + BB*256*PP + BB*PP;  // 794624
    k_out<<<(total + 255)/256, 256>>>(out, xyz, inds);
}

// round 5
// speedup vs baseline: 1.6978x; 1.3791x over previous
#include <cuda_runtime.h>
#include <math.h>

// Problem constants
#define BB   8
#define NN   20000
#define NPAD 20096        // 157 * 128
#define PP   256
#define SS   32
#define CC   256
#define NCC  18
#define BP   (BB*PP)      // 2048

// ---------------- scratch (__device__ globals; no allocation allowed) ---------------
// NOTE: never pass these as kernel arguments from host code -- host-side symbol
// addresses are NOT device addresses (ATS makes the bug silent on GB300).
__device__ int   g_sel[BP*SS];
__device__ float g_nf [BP*128];
__device__ float g_lf [BP*256];
__device__ float g_ss [BB*256];
__device__ float g_ss2[BB*512];
__device__ __align__(16) float g_sx[BB*NPAD];
__device__ __align__(16) float g_sy[BB*NPAD];
__device__ __align__(16) float g_sz[BB*NPAD];
__device__ float g_e1[BB*128], g_e2[BB*256];
__device__ float g_t1[BB*512], g_t2[BB*1024];
__device__ float g_s1[BB*512], g_s2[BB*1024];

// transposed weights: layout [K][O] (wt[c*O + o]) -- point/label MLP weights only
__device__ __align__(16) float g_mw0t [259*128];
__device__ __align__(16) float g_mw1t [128*128];
__device__ __align__(16) float g_mw2t [128*128];
__device__ __align__(16) float g_lw0t [146*256];
__device__ __align__(16) float g_lw1t [256*256];
__device__ __align__(16) float g_lw2t [256*256];

// ---------------- activations --------------------------------------------------------
__device__ __forceinline__ float gelu_exact(float x) {
    return 0.5f * x * (1.0f + erff(x * 0.70710678118654752f));
}
__device__ __forceinline__ float silu_f(float x) { return x / (1.0f + expf(-x)); }

// ---------------- kernel T: fused tiled transpose of the 6 MLP weights --------------
__global__ void k_transpose_all(const float* __restrict__ mw0, const float* __restrict__ mw1,
                                const float* __restrict__ mw2, const float* __restrict__ lw0,
                                const float* __restrict__ lw1, const float* __restrict__ lw2) {
    int t = blockIdx.x;
    const float* src; float* dst; int O, K, base;
    if      (t < 36)  { src = mw0; dst = g_mw0t; O = 128; K = 259; base = 0;   }
    else if (t < 52)  { src = mw1; dst = g_mw1t; O = 128; K = 128; base = 36;  }
    else if (t < 68)  { src = mw2; dst = g_mw2t; O = 128; K = 128; base = 52;  }
    else if (t < 108) { src = lw0; dst = g_lw0t; O = 256; K = 146; base = 68;  }
    else if (t < 172) { src = lw1; dst = g_lw1t; O = 256; K = 256; base = 108; }
    else              { src = lw2; dst = g_lw2t; O = 256; K = 256; base = 172; }
    int tile = t - base;
    int ntk = (K + 31) >> 5;
    int kt = tile % ntk, ot = tile / ntk;
    __shared__ float s[32][33];
    int k0 = kt * 32, o0 = ot * 32;
    int tx = threadIdx.x, ty = threadIdx.y;   // 32 x 8
    #pragma unroll
    for (int i = ty; i < 32; i += 8) {
        int o = o0 + i, k = k0 + tx;
        if (o < O && k < K) s[i][tx] = src[o * K + k];
    }
    __syncthreads();
    #pragma unroll
    for (int i = ty; i < 32; i += 8) {
        int k = k0 + i, o = o0 + tx;
        if (k < K && o < O) dst[k * O + o] = s[tx][i];
    }
}

// ---------------- kernel S0: AoS -> SoA with sentinel padding ------------------------
__global__ void k_soa(const float* __restrict__ xyz) {
    int i = blockIdx.x * 256 + threadIdx.x;
    if (i >= BB * NPAD) return;
    int b = i / NPAD, n = i - b * NPAD;
    float x = 3e38f, y = 3e38f, z = 3e38f;
    if (n < NN) {
        const float* p = xyz + ((size_t)b * NN + n) * 3;
        x = p[0]; y = p[1]; z = p[2];
    }
    g_sx[i] = x; g_sy[i] = y; g_sz[i] = z;
}

// ---------------- kernel A: in-box sampling (2 warps/block, prefetch, early exit) ---
__global__ void __launch_bounds__(64) k_sample(const float* __restrict__ xyz,
                         const float* __restrict__ bsize,
                         const int*   __restrict__ inds) {
    __shared__ int buf[2][SS];
    int lane = threadIdx.x & 31, w = threadIdx.x >> 5;
    int q = blockIdx.x * 2 + w;
    int b = q >> 8;
    int n0 = inds[q];
    const float* cp = xyz + ((size_t)b * NN + n0) * 3;
    float cx = cp[0], cy = cp[1], cz = cp[2];
    float hx = bsize[q*3+0]*0.5f, hy = bsize[q*3+1]*0.5f, hz = bsize[q*3+2]*0.5f;
    const float4* X = (const float4*)(g_sx + b * NPAD);
    const float4* Y = (const float4*)(g_sy + b * NPAD);
    const float4* Z = (const float4*)(g_sz + b * NPAD);

    unsigned below = (1u << lane) - 1u;
    int found = 0;
    float4 xs = X[lane], ys = Y[lane], zs = Z[lane];
    for (int it = 0; it < NPAD/128; it++) {        // 157 iters
        float4 nx, ny, nz;
        if (it + 1 < NPAD/128) {                   // prefetch next chunk before ballots
            int v = (it + 1) * 32 + lane;
            nx = X[v]; ny = Y[v]; nz = Z[v];
        }
        bool i0 = (fabsf(xs.x-cx)<=hx) && (fabsf(ys.x-cy)<=hy) && (fabsf(zs.x-cz)<=hz);
        bool i1 = (fabsf(xs.y-cx)<=hx) && (fabsf(ys.y-cy)<=hy) && (fabsf(zs.y-cz)<=hz);
        bool i2 = (fabsf(xs.z-cx)<=hx) && (fabsf(ys.z-cy)<=hy) && (fabsf(zs.z-cz)<=hz);
        bool i3 = (fabsf(xs.w-cx)<=hx) && (fabsf(ys.w-cy)<=hy) && (fabsf(zs.w-cz)<=hz);
        unsigned m0 = __ballot_sync(0xffffffffu, i0);
        unsigned m1 = __ballot_sync(0xffffffffu, i1);
        unsigned m2 = __ballot_sync(0xffffffffu, i2);
        unsigned m3 = __ballot_sync(0xffffffffu, i3);
        if (m0 | m1 | m2 | m3) {
            int pre = found
                    + __popc(m0 & below) + __popc(m1 & below)
                    + __popc(m2 & below) + __popc(m3 & below);
            int np = it * 128 + 4 * lane;
            unsigned b0 = (m0 >> lane) & 1u, b1 = (m1 >> lane) & 1u, b2 = (m2 >> lane) & 1u;
            if (i0 && pre < SS)                    buf[w][pre] = np;
            int r1 = pre + (int)b0;
            if (i1 && r1 < SS)                     buf[w][r1] = np + 1;
            int r2 = r1 + (int)b1;
            if (i2 && r2 < SS)                     buf[w][r2] = np + 2;
            int r3 = r2 + (int)b2;
            if (i3 && r3 < SS)                     buf[w][r3] = np + 3;
        }
        found += __popc(m0) + __popc(m1) + __popc(m2) + __popc(m3);
        if (found >= SS) break;                    // warp-uniform
        xs = nx; ys = ny; zs = nz;
    }
    __syncwarp();
    int eff = found < SS ? found : SS;
    int sel = 0;
    if (eff > 0) sel = buf[w][lane % eff];
    g_sel[q*SS + lane] = sel;
}

// ---------------- time-MLP chain: embeddings + 3 GEMV stage kernels -----------------
__global__ void k_emb(const float* __restrict__ ts) {  // grid BB, block 128
    int b = blockIdx.x, tid = threadIdx.x;
    float t = ts[b];
    if (tid < 64) {
        float f = expf(tid * (-9.210340371976184f/63.0f));
        float e = t * f;
        g_e1[b*128 + tid] = sinf(e); g_e1[b*128 + 64 + tid] = cosf(e);
    }
    {
        float f = expf(tid * (-9.210340371976184f/127.0f));
        float e = t * f;
        g_e2[b*256 + tid] = sinf(e); g_e2[b*256 + 128 + tid] = cosf(e);
    }
}

// One block = 32 rows x 8 batches. Weights staged in smem, read once from L2/DRAM.
// Scratch in/out pointers resolved IN DEVICE CODE from `stage` (0,1,2) + side.
__global__ void k_tstage(const float* __restrict__ WA, const float* __restrict__ bA,
                         const float* __restrict__ WB, const float* __restrict__ bB,
                         int RA, int stage) {
    extern __shared__ float dsm[];
    int blk = blockIdx.x;
    int nA = RA >> 5;
    bool isA = blk < nA;
    const float *W = isA ? WA : WB;
    const float *bias = isA ? bA : bB;
    int row0 = (isA ? blk : blk - nA) << 5;
    const float* gin; float* gout; int K, R; int act;
    if (stage == 0) {
        act = 0;
        if (isA) { gin = g_e1; gout = g_t1; K = 128;  R = 512;  }
        else     { gin = g_e2; gout = g_t2; K = 256;  R = 1024; }
    } else if (stage == 1) {
        act = 1;
        if (isA) { gin = g_t1; gout = g_s1; K = 512;  R = 512;  }
        else     { gin = g_t2; gout = g_s2; K = 1024; R = 1024; }
    } else {
        act = 2;
        if (isA) { gin = g_s1; gout = g_ss;  K = 512;  R = 256; }
        else     { gin = g_s2; gout = g_ss2; K = 1024; R = 512; }
    }
    float* in_s = dsm;                 // [8][K+4]
    float* w_s  = dsm + 8 * (K + 4);   // [32][132]
    int tid = threadIdx.x;             // 256
    int rl = tid >> 3, bb = tid & 7;
    int stride = K + 4;
    int ksh = __ffs(K) - 1;            // K is a power of two (128..1024)
    for (int i = tid; i < (K << 3); i += 256) {
        int b2 = i >> ksh, c = i & (K - 1);
        in_s[b2 * stride + c] = gin[i];
    }
    float acc = 0.0f;
    for (int ko = 0; ko < K; ko += 128) {
        __syncthreads();
        #pragma unroll
        for (int i = tid; i < 1024; i += 256) {      // 32 rows x 128 cols as float4
            int r = i >> 5, c4 = i & 31;
            float4 v = *(const float4*)(W + (size_t)(row0 + r) * K + ko + c4 * 4);
            *(float4*)&w_s[r * 132 + c4 * 4] = v;
        }
        __syncthreads();
        const float* wr = w_s + rl * 132;
        const float* ir = in_s + bb * stride + ko;
        #pragma unroll 8
        for (int c = 0; c < 128; c++) acc += wr[c] * ir[c];
    }
    acc += bias[row0 + rl];
    if (act == 0) acc = gelu_exact(acc);
    else if (act == 1) acc = silu_f(acc);
    gout[bb * R + row0 + rl] = acc;
}

// ---------------- kernel B: register-tiled point MLP + maxpool + label MLP ----------
// Block = 2 proposals (64 points) x 128 outputs; 512 threads, 4pts x 4outs per thread.
// Activations channel-major in smem: in[c][pt]; weights [c][128] via half-warp-uniform
// LDG.128. Per K-step per thread: 1 LDS.128 + 1 LDG.128 + 16 FFMA.
#define OS 68   // output row stride (floats); 68*4 bytes % 16 == 0, 4-way-bounded banks

__device__ __forceinline__ float relu_f(float x) { return fmaxf(x, 0.0f); }

template<int K, int IS>
__device__ __forceinline__ void layerT(const float* __restrict__ in,
                                       const float* __restrict__ wt,
                                       const float* __restrict__ bias,
                                       float* __restrict__ out,
                                       int pg, int oq) {
    float4 bq = reinterpret_cast<const float4*>(bias)[oq];
    float a00=bq.x, a01=bq.y, a02=bq.z, a03=bq.w;
    float a10=bq.x, a11=bq.y, a12=bq.z, a13=bq.w;
    float a20=bq.x, a21=bq.y, a22=bq.z, a23=bq.w;
    float a30=bq.x, a31=bq.y, a32=bq.z, a33=bq.w;
    const float* ip = in + 4*pg;
    const float* wp = wt + 4*oq;
    #pragma unroll 2
    for (int c = 0; c < K; c++) {
        float4 x = *(const float4*)(ip + c*IS);
        float4 w = *(const float4*)(wp + c*128);
        a00 += x.x*w.x; a01 += x.x*w.y; a02 += x.x*w.z; a03 += x.x*w.w;
        a10 += x.y*w.x; a11 += x.y*w.y; a12 += x.y*w.z; a13 += x.y*w.w;
        a20 += x.z*w.x; a21 += x.z*w.y; a22 += x.z*w.z; a23 += x.z*w.w;
        a30 += x.w*w.x; a31 += x.w*w.y; a32 += x.w*w.z; a33 += x.w*w.w;
    }
    float* o = out + 4*pg;
    *(float4*)(o + (4*oq+0)*OS) = make_float4(relu_f(a00), relu_f(a10), relu_f(a20), relu_f(a30));
    *(float4*)(o + (4*oq+1)*OS) = make_float4(relu_f(a01), relu_f(a11), relu_f(a21), relu_f(a31));
    *(float4*)(o + (4*oq+2)*OS) = make_float4(relu_f(a02), relu_f(a12), relu_f(a22), relu_f(a32));
    *(float4*)(o + (4*oq+3)*OS) = make_float4(relu_f(a03), relu_f(a13), relu_f(a23), relu_f(a33));
}

__global__ void __launch_bounds__(512, 2) k_mlp(
                      const float* __restrict__ xyz, const float* __restrict__ feat,
                      const int* __restrict__ inds,
                      const float* __restrict__ mb0, const float* __restrict__ mb1,
                      const float* __restrict__ mb2,
                      const float* __restrict__ blabel,
                      const float* __restrict__ lb0, const float* __restrict__ lb1,
                      const float* __restrict__ lb2) {
    extern __shared__ float sm[];
    float* g  = sm;                     // [259][64] layer0 input; reused as hB [128][OS]
    float* hA = sm + 259*64;            // [128][OS]
    __shared__ int   sidx[64];
    __shared__ float ctr[2][3];
    __shared__ float in0[2][152];
    __shared__ float hL1[2][256], hL2[2][256];

    int q0 = blockIdx.x * 2, b = q0 >> 8;    // both proposals in same batch (PP even)
    int tid = threadIdx.x;                   // 512 threads
    if (tid < 64) sidx[tid] = g_sel[(q0 + (tid >> 5))*SS + (tid & 31)];
    if (tid < 6) {
        int pr = tid / 3, d = tid - pr*3;
        int n0 = inds[q0 + pr];
        ctr[pr][d] = xyz[((size_t)b*NN + n0)*3 + d];
    }
    if (tid < 2*NCC) {
        int pr = tid / NCC, c = tid - pr*NCC;
        in0[pr][c] = blabel[(q0 + pr)*NCC + c];
    }
    __syncthreads();

    // gather: g[3+c][s] = feat[b][c][sidx[s]] ; g[d][s] = xyz - ctr
    const float* fb = feat + (size_t)b * CC * NN;
    for (int i = tid; i < 64 * CC; i += 512) {
        int s = i & 63, c = i >> 6;
        g[(3 + c)*64 + s] = __ldg(fb + (size_t)c * NN + sidx[s]);
    }
    if (tid < 192) {
        int s = tid & 63, d = tid >> 6, pr = s >> 5;
        g[d*64 + s] = xyz[((size_t)b*NN + sidx[s])*3 + d] - ctr[pr][d];
    }
    __syncthreads();

    int pg = tid & 15, oq = tid >> 4;       // pg in [0,16), oq in [0,32)
    layerT<259, 64>(g,  g_mw0t, mb0, hA, pg, oq); __syncthreads();
    layerT<128, OS>(hA, g_mw1t, mb1, g,  pg, oq); __syncthreads();
    layerT<128, OS>(g,  g_mw2t, mb2, hA, pg, oq); __syncthreads();

    // maxpool over 32 samples per proposal (relu outputs >= 0)
    if (tid < 256) {
        int o = tid & 127, pr = tid >> 7;
        const float* r = hA + o*OS + pr*32;
        float m = 0.0f;
        #pragma unroll
        for (int j = 0; j < 32; j += 4) {
            float4 v = *(const float4*)(r + j);
            m = fmaxf(m, fmaxf(fmaxf(v.x, v.y), fmaxf(v.z, v.w)));
        }
        g_nf[(q0 + pr)*128 + o] = m;
        in0[pr][NCC + o] = m;
    }
    __syncthreads();

    // fused label MLP: 146 -> 256 -> 256 -> 256 ; thread = (proposal, output)
    {
        int o = tid & 255, pr = tid >> 8;
        const float* inp = in0[pr];
        float acc = lb0[o];
        #pragma unroll 2
        for (int c = 0; c < 146; c++) acc += inp[c] * g_lw0t[c*256 + o];
        hL1[pr][o] = relu_f(acc);
        __syncthreads();
        acc = lb1[o];
        const float* h1 = hL1[pr];
        #pragma unroll 4
        for (int c = 0; c < 256; c++) acc += h1[c] * g_lw1t[c*256 + o];
        hL2[pr][o] = relu_f(acc);
        __syncthreads();
        acc = lb2[o];
        const float* h2 = hL2[pr];
        #pragma unroll 4
        for (int c = 0; c < 256; c++) acc += h2[c] * g_lw2t[c*256 + o];
        g_lf[(q0 + pr)*256 + o] = relu_f(acc);
    }
}

// ---------------- kernel D: FiLM + all outputs ---------------------------------------
// FiLM index collapse (verified): scale index d' = (d*P + p) mod D
//   D=128, P=256 -> d' = p % 128 ;  D=256, P=256 -> d' = p
__global__ void k_out(float* __restrict__ out, const float* __restrict__ xyz,
                      const int* __restrict__ inds) {
    const int O0 = BB*PP*3;           // 6144
    const int O1 = O0 + BB*128*PP;    // 268288
    const int O2 = O1 + BB*256*PP;    // 792576
    const int O3 = O2 + BB*PP;        // 794624
    int i = blockIdx.x * blockDim.x + threadIdx.x;
    if (i < O0) {
        int b = i / (PP*3); int r = i - b*(PP*3); int p = r/3, d = r - p*3;
        out[i] = xyz[((size_t)b*NN + inds[b*PP + p])*3 + d];
    } else if (i < O1) {
        int j = i - O0;
        int b = j >> 15;
        int r = j & 32767;
        int d = r >> 8, p = r & 255;
        int m = p & 127;
        out[i] = g_nf[((b<<8) + p)*128 + d] * (g_ss[b*256 + m] + 1.0f)
               + g_ss[b*256 + 128 + m];
    } else if (i < O2) {
        int j = i - O1;
        int b = j >> 16;
        int r = j & 65535;
        int d = r >> 8, p = r & 255;
        out[i] = g_lf[((b<<8) + p)*256 + d] * (g_ss2[b*512 + p] + 1.0f)
               + g_ss2[b*512 + 256 + p];
    } else if (i < O3) {
        out[i] = (float)inds[i - O2];
    }
}

// ---------------- launcher -----------------------------------------------------------
extern "C" void kernel_launch(void* const* d_in, const int* in_sizes, int n_in,
                              void* d_out, int out_size) {
    const float* xyz    = (const float*)d_in[0];
    const float* feat   = (const float*)d_in[1];
    const float* bsize  = (const float*)d_in[2];
    const float* blabel = (const float*)d_in[3];
    const float* ts     = (const float*)d_in[4];
    const int*   inds   = (const int*)  d_in[5];
    const float* mw0 = (const float*)d_in[6],  *mb0 = (const float*)d_in[7];
    const float* mw1 = (const float*)d_in[8],  *mb1 = (const float*)d_in[9];
    const float* mw2 = (const float*)d_in[10], *mb2 = (const float*)d_in[11];
    const float* lw0 = (const float*)d_in[12], *lb0 = (const float*)d_in[13];
    const float* lw1 = (const float*)d_in[14], *lb1 = (const float*)d_in[15];
    const float* lw2 = (const float*)d_in[16], *lb2 = (const float*)d_in[17];
    const float* tw0 = (const float*)d_in[18], *tb0 = (const float*)d_in[19];
    const float* tw1 = (const float*)d_in[20], *tb1 = (const float*)d_in[21];
    const float* bw  = (const float*)d_in[22], *bbv = (const float*)d_in[23];
    const float* tlw0= (const float*)d_in[24], *tlb0= (const float*)d_in[25];
    const float* tlw1= (const float*)d_in[26], *tlb1= (const float*)d_in[27];
    const float* blw = (const float*)d_in[28], *blb = (const float*)d_in[29];
    float* out = (float*)d_out;

    dim3 tb(32, 8);
    k_transpose_all<<<236, tb>>>(mw0, mw1, mw2, lw0, lw1, lw2);
    k_soa<<<(BB*NPAD + 255)/256, 256>>>(xyz);
    k_emb<<<BB, 128>>>(ts);
    k_sample<<<BP/2, 64>>>(xyz, bsize, inds);

    int smem_t = (8*(1024+4) + 32*132) * (int)sizeof(float);   // 49792 B
    cudaFuncSetAttribute(k_tstage, cudaFuncAttributeMaxDynamicSharedMemorySize, smem_t);
    k_tstage<<<48, 256, smem_t>>>(tw0, tb0, tlw0, tlb0, 512, 0);

    int smem_b = (259*64 + 128*OS) * (int)sizeof(float);       // 101120 B
    cudaFuncSetAttribute(k_mlp, cudaFuncAttributeMaxDynamicSharedMemorySize, smem_b);
    k_mlp<<<BP/2, 512, smem_b>>>(xyz, feat, inds, mb0, mb1, mb2,
                                 blabel, lb0, lb1, lb2);

    k_tstage<<<48, 256, smem_t>>>(tw1, tb1, tlw1, tlb1, 512, 1);
    k_tstage<<<24, 256, smem_t>>>(bw,  bbv, blw,  blb,  256, 2);

    const int total = BB*PP*3 + BB*128*PP + BB*256*PP + BB*PP;  // 794624
    k_out<<<(total + 255)/256, 256>>>(out, xyz, inds);
}

// round 6
// speedup vs baseline: 1.7041x; 1.0037x over previous
#include <cuda_runtime.h>
#include <math.h>

// Problem constants
#define BB   8
#define NN   20000
#define NPAD 20096        // 157 * 128
#define PP   256
#define SS   32
#define CC   256
#define NCC  18
#define BP   (BB*PP)      // 2048

// ---------------- scratch (__device__ globals; no allocation allowed) ---------------
// NOTE: never pass these as kernel arguments from host code -- host-side symbol
// addresses are NOT device addresses (ATS makes the bug silent on GB300).
__device__ int   g_sel[BP*SS];
__device__ float g_nf [BP*128];
__device__ float g_lf [BP*256];
__device__ float g_ss [BB*256];
__device__ float g_ss2[BB*512];
__device__ __align__(16) float g_sx[BB*NPAD];
__device__ __align__(16) float g_sy[BB*NPAD];
__device__ __align__(16) float g_sz[BB*NPAD];
__device__ float g_e1[BB*128], g_e2[BB*256];
__device__ float g_t1[BB*512], g_t2[BB*1024];
__device__ float g_s1[BB*512], g_s2[BB*1024];

// transposed weights: layout [K][O] (wt[c*O + o]) -- point/label MLP weights only
__device__ __align__(16) float g_mw0t [259*128];
__device__ __align__(16) float g_mw1t [128*128];
__device__ __align__(16) float g_mw2t [128*128];
__device__ __align__(16) float g_lw0t [146*256];
__device__ __align__(16) float g_lw1t [256*256];
__device__ __align__(16) float g_lw2t [256*256];

// ---------------- activations --------------------------------------------------------
__device__ __forceinline__ float gelu_exact(float x) {
    return 0.5f * x * (1.0f + erff(x * 0.70710678118654752f));
}
__device__ __forceinline__ float silu_f(float x) { return x / (1.0f + expf(-x)); }

// ---------------- kernel T: fused tiled transpose of the 6 MLP weights --------------
__global__ void k_transpose_all(const float* __restrict__ mw0, const float* __restrict__ mw1,
                                const float* __restrict__ mw2, const float* __restrict__ lw0,
                                const float* __restrict__ lw1, const float* __restrict__ lw2) {
    int t = blockIdx.x;
    const float* src; float* dst; int O, K, base;
    if      (t < 36)  { src = mw0; dst = g_mw0t; O = 128; K = 259; base = 0;   }
    else if (t < 52)  { src = mw1; dst = g_mw1t; O = 128; K = 128; base = 36;  }
    else if (t < 68)  { src = mw2; dst = g_mw2t; O = 128; K = 128; base = 52;  }
    else if (t < 108) { src = lw0; dst = g_lw0t; O = 256; K = 146; base = 68;  }
    else if (t < 172) { src = lw1; dst = g_lw1t; O = 256; K = 256; base = 108; }
    else              { src = lw2; dst = g_lw2t; O = 256; K = 256; base = 172; }
    int tile = t - base;
    int ntk = (K + 31) >> 5;
    int kt = tile % ntk, ot = tile / ntk;
    __shared__ float s[32][33];
    int k0 = kt * 32, o0 = ot * 32;
    int tx = threadIdx.x, ty = threadIdx.y;   // 32 x 8
    #pragma unroll
    for (int i = ty; i < 32; i += 8) {
        int o = o0 + i, k = k0 + tx;
        if (o < O && k < K) s[i][tx] = src[o * K + k];
    }
    __syncthreads();
    #pragma unroll
    for (int i = ty; i < 32; i += 8) {
        int k = k0 + i, o = o0 + tx;
        if (k < K && o < O) dst[k * O + o] = s[tx][i];
    }
}

// ---------------- kernel S0: AoS -> SoA with sentinel padding ------------------------
__global__ void k_soa(const float* __restrict__ xyz) {
    int i = blockIdx.x * 256 + threadIdx.x;
    if (i >= BB * NPAD) return;
    int b = i / NPAD, n = i - b * NPAD;
    float x = 3e38f, y = 3e38f, z = 3e38f;
    if (n < NN) {
        const float* p = xyz + ((size_t)b * NN + n) * 3;
        x = p[0]; y = p[1]; z = p[2];
    }
    g_sx[i] = x; g_sy[i] = y; g_sz[i] = z;
}

// ---------------- kernel A: in-box sampling (2 warps/block, prefetch, early exit) ---
__global__ void __launch_bounds__(64) k_sample(const float* __restrict__ xyz,
                         const float* __restrict__ bsize,
                         const int*   __restrict__ inds) {
    __shared__ int buf[2][SS];
    int lane = threadIdx.x & 31, w = threadIdx.x >> 5;
    int q = blockIdx.x * 2 + w;
    int b = q >> 8;
    int n0 = inds[q];
    const float* cp = xyz + ((size_t)b * NN + n0) * 3;
    float cx = cp[0], cy = cp[1], cz = cp[2];
    float hx = bsize[q*3+0]*0.5f, hy = bsize[q*3+1]*0.5f, hz = bsize[q*3+2]*0.5f;
    const float4* X = (const float4*)(g_sx + b * NPAD);
    const float4* Y = (const float4*)(g_sy + b * NPAD);
    const float4* Z = (const float4*)(g_sz + b * NPAD);

    unsigned below = (1u << lane) - 1u;
    int found = 0;
    float4 xs = X[lane], ys = Y[lane], zs = Z[lane];
    for (int it = 0; it < NPAD/128; it++) {        // 157 iters
        float4 nx, ny, nz;
        if (it + 1 < NPAD/128) {                   // prefetch next chunk before ballots
            int v = (it + 1) * 32 + lane;
            nx = X[v]; ny = Y[v]; nz = Z[v];
        }
        bool i0 = (fabsf(xs.x-cx)<=hx) && (fabsf(ys.x-cy)<=hy) && (fabsf(zs.x-cz)<=hz);
        bool i1 = (fabsf(xs.y-cx)<=hx) && (fabsf(ys.y-cy)<=hy) && (fabsf(zs.y-cz)<=hz);
        bool i2 = (fabsf(xs.z-cx)<=hx) && (fabsf(ys.z-cy)<=hy) && (fabsf(zs.z-cz)<=hz);
        bool i3 = (fabsf(xs.w-cx)<=hx) && (fabsf(ys.w-cy)<=hy) && (fabsf(zs.w-cz)<=hz);
        unsigned m0 = __ballot_sync(0xffffffffu, i0);
        unsigned m1 = __ballot_sync(0xffffffffu, i1);
        unsigned m2 = __ballot_sync(0xffffffffu, i2);
        unsigned m3 = __ballot_sync(0xffffffffu, i3);
        if (m0 | m1 | m2 | m3) {
            int pre = found
                    + __popc(m0 & below) + __popc(m1 & below)
                    + __popc(m2 & below) + __popc(m3 & below);
            int np = it * 128 + 4 * lane;
            unsigned b0 = (m0 >> lane) & 1u, b1 = (m1 >> lane) & 1u, b2 = (m2 >> lane) & 1u;
            if (i0 && pre < SS)                    buf[w][pre] = np;
            int r1 = pre + (int)b0;
            if (i1 && r1 < SS)                     buf[w][r1] = np + 1;
            int r2 = r1 + (int)b1;
            if (i2 && r2 < SS)                     buf[w][r2] = np + 2;
            int r3 = r2 + (int)b2;
            if (i3 && r3 < SS)                     buf[w][r3] = np + 3;
        }
        found += __popc(m0) + __popc(m1) + __popc(m2) + __popc(m3);
        if (found >= SS) break;                    // warp-uniform
        xs = nx; ys = ny; zs = nz;
    }
    __syncwarp();
    int eff = found < SS ? found : SS;
    int sel = 0;
    if (eff > 0) sel = buf[w][lane % eff];
    g_sel[q*SS + lane] = sel;
}

// ---------------- time-MLP chain: embeddings + 3 GEMV stage kernels -----------------
__global__ void k_emb(const float* __restrict__ ts) {  // grid BB, block 128
    int b = blockIdx.x, tid = threadIdx.x;
    float t = ts[b];
    if (tid < 64) {
        float f = expf(tid * (-9.210340371976184f/63.0f));
        float e = t * f;
        g_e1[b*128 + tid] = sinf(e); g_e1[b*128 + 64 + tid] = cosf(e);
    }
    {
        float f = expf(tid * (-9.210340371976184f/127.0f));
        float e = t * f;
        g_e2[b*256 + tid] = sinf(e); g_e2[b*256 + 128 + tid] = cosf(e);
    }
}

// One block = 32 rows x 8 batches. Weights staged in smem, read once from L2/DRAM.
// Scratch in/out pointers resolved IN DEVICE CODE from `stage` (0,1,2) + side.
__global__ void k_tstage(const float* __restrict__ WA, const float* __restrict__ bA,
                         const float* __restrict__ WB, const float* __restrict__ bB,
                         int RA, int stage) {
    extern __shared__ float dsm[];
    int blk = blockIdx.x;
    int nA = RA >> 5;
    bool isA = blk < nA;
    const float *W = isA ? WA : WB;
    const float *bias = isA ? bA : bB;
    int row0 = (isA ? blk : blk - nA) << 5;
    const float* gin; float* gout; int K, R; int act;
    if (stage == 0) {
        act = 0;
        if (isA) { gin = g_e1; gout = g_t1; K = 128;  R = 512;  }
        else     { gin = g_e2; gout = g_t2; K = 256;  R = 1024; }
    } else if (stage == 1) {
        act = 1;
        if (isA) { gin = g_t1; gout = g_s1; K = 512;  R = 512;  }
        else     { gin = g_t2; gout = g_s2; K = 1024; R = 1024; }
    } else {
        act = 2;
        if (isA) { gin = g_s1; gout = g_ss;  K = 512;  R = 256; }
        else     { gin = g_s2; gout = g_ss2; K = 1024; R = 512; }
    }
    float* in_s = dsm;                 // [8][K+4]
    float* w_s  = dsm + 8 * (K + 4);   // [32][132]
    int tid = threadIdx.x;             // 256
    int rl = tid >> 3, bb = tid & 7;
    int stride = K + 4;
    int ksh = __ffs(K) - 1;            // K is a power of two (128..1024)
    for (int i = tid; i < (K << 3); i += 256) {
        int b2 = i >> ksh, c = i & (K - 1);
        in_s[b2 * stride + c] = gin[i];
    }
    float acc = 0.0f;
    for (int ko = 0; ko < K; ko += 128) {
        __syncthreads();
        #pragma unroll
        for (int i = tid; i < 1024; i += 256) {      // 32 rows x 128 cols as float4
            int r = i >> 5, c4 = i & 31;
            float4 v = *(const float4*)(W + (size_t)(row0 + r) * K + ko + c4 * 4);
            *(float4*)&w_s[r * 132 + c4 * 4] = v;
        }
        __syncthreads();
        const float* wr = w_s + rl * 132;
        const float* ir = in_s + bb * stride + ko;
        #pragma unroll 8
        for (int c = 0; c < 128; c++) acc += wr[c] * ir[c];
    }
    acc += bias[row0 + rl];
    if (act == 0) acc = gelu_exact(acc);
    else if (act == 1) acc = silu_f(acc);
    gout[bb * R + row0 + rl] = acc;
}

// ---------------- kernel B: register-tiled point MLP + maxpool + label MLP ----------
// Block = 2 proposals (64 points) x 128 outputs; 512 threads, 4pts x 4outs per thread.
// Activations channel-major in smem: in[c][pt]; weights [c][128] via half-warp-uniform
// LDG.128. Per K-step per thread: 1 LDS.128 + 1 LDG.128 + 16 FFMA.
#define OS 68   // output row stride (floats); 68*4 bytes % 16 == 0, 4-way-bounded banks

__device__ __forceinline__ float relu_f(float x) { return fmaxf(x, 0.0f); }

template<int K, int IS>
__device__ __forceinline__ void layerT(const float* __restrict__ in,
                                       const float* __restrict__ wt,
                                       const float* __restrict__ bias,
                                       float* __restrict__ out,
                                       int pg, int oq) {
    float4 bq = reinterpret_cast<const float4*>(bias)[oq];
    float a00=bq.x, a01=bq.y, a02=bq.z, a03=bq.w;
    float a10=bq.x, a11=bq.y, a12=bq.z, a13=bq.w;
    float a20=bq.x, a21=bq.y, a22=bq.z, a23=bq.w;
    float a30=bq.x, a31=bq.y, a32=bq.z, a33=bq.w;
    const float* ip = in + 4*pg;
    const float* wp = wt + 4*oq;
    #pragma unroll 2
    for (int c = 0; c < K; c++) {
        float4 x = *(const float4*)(ip + c*IS);
        float4 w = *(const float4*)(wp + c*128);
        a00 += x.x*w.x; a01 += x.x*w.y; a02 += x.x*w.z; a03 += x.x*w.w;
        a10 += x.y*w.x; a11 += x.y*w.y; a12 += x.y*w.z; a13 += x.y*w.w;
        a20 += x.z*w.x; a21 += x.z*w.y; a22 += x.z*w.z; a23 += x.z*w.w;
        a30 += x.w*w.x; a31 += x.w*w.y; a32 += x.w*w.z; a33 += x.w*w.w;
    }
    float* o = out + 4*pg;
    *(float4*)(o + (4*oq+0)*OS) = make_float4(relu_f(a00), relu_f(a10), relu_f(a20), relu_f(a30));
    *(float4*)(o + (4*oq+1)*OS) = make_float4(relu_f(a01), relu_f(a11), relu_f(a21), relu_f(a31));
    *(float4*)(o + (4*oq+2)*OS) = make_float4(relu_f(a02), relu_f(a12), relu_f(a22), relu_f(a32));
    *(float4*)(o + (4*oq+3)*OS) = make_float4(relu_f(a03), relu_f(a13), relu_f(a23), relu_f(a33));
}

__global__ void __launch_bounds__(512, 2) k_mlp(
                      const float* __restrict__ xyz, const float* __restrict__ feat,
                      const int* __restrict__ inds,
                      const float* __restrict__ mb0, const float* __restrict__ mb1,
                      const float* __restrict__ mb2,
                      const float* __restrict__ blabel,
                      const float* __restrict__ lb0, const float* __restrict__ lb1,
                      const float* __restrict__ lb2) {
    extern __shared__ float sm[];
    float* g  = sm;                     // [259][64] layer0 input; reused as hB [128][OS]
    float* hA = sm + 259*64;            // [128][OS]
    __shared__ int   sidx[64];
    __shared__ float ctr[2][3];
    __shared__ float in0[2][152];
    __shared__ float hL1[2][256], hL2[2][256];

    int q0 = blockIdx.x * 2, b = q0 >> 8;    // both proposals in same batch (PP even)
    int tid = threadIdx.x;                   // 512 threads
    if (tid < 64) sidx[tid] = g_sel[(q0 + (tid >> 5))*SS + (tid & 31)];
    if (tid < 6) {
        int pr = tid / 3, d = tid - pr*3;
        int n0 = inds[q0 + pr];
        ctr[pr][d] = xyz[((size_t)b*NN + n0)*3 + d];
    }
    if (tid < 2*NCC) {
        int pr = tid / NCC, c = tid - pr*NCC;
        in0[pr][c] = blabel[(q0 + pr)*NCC + c];
    }
    __syncthreads();

    // gather: g[3+c][s] = feat[b][c][sidx[s]] ; g[d][s] = xyz - ctr
    const float* fb = feat + (size_t)b * CC * NN;
    for (int i = tid; i < 64 * CC; i += 512) {
        int s = i & 63, c = i >> 6;
        g[(3 + c)*64 + s] = __ldg(fb + (size_t)c * NN + sidx[s]);
    }
    if (tid < 192) {
        int s = tid & 63, d = tid >> 6, pr = s >> 5;
        g[d*64 + s] = xyz[((size_t)b*NN + sidx[s])*3 + d] - ctr[pr][d];
    }
    __syncthreads();

    int pg = tid & 15, oq = tid >> 4;       // pg in [0,16), oq in [0,32)
    layerT<259, 64>(g,  g_mw0t, mb0, hA, pg, oq); __syncthreads();
    layerT<128, OS>(hA, g_mw1t, mb1, g,  pg, oq); __syncthreads();
    layerT<128, OS>(g,  g_mw2t, mb2, hA, pg, oq); __syncthreads();

    // maxpool over 32 samples per proposal (relu outputs >= 0)
    if (tid < 256) {
        int o = tid & 127, pr = tid >> 7;
        const float* r = hA + o*OS + pr*32;
        float m = 0.0f;
        #pragma unroll
        for (int j = 0; j < 32; j += 4) {
            float4 v = *(const float4*)(r + j);
            m = fmaxf(m, fmaxf(fmaxf(v.x, v.y), fmaxf(v.z, v.w)));
        }
        g_nf[(q0 + pr)*128 + o] = m;
        in0[pr][NCC + o] = m;
    }
    __syncthreads();

    // fused label MLP: 146 -> 256 -> 256 -> 256 ; thread = (proposal, output)
    {
        int o = tid & 255, pr = tid >> 8;
        const float* inp = in0[pr];
        float acc = lb0[o];
        #pragma unroll 2
        for (int c = 0; c < 146; c++) acc += inp[c] * g_lw0t[c*256 + o];
        hL1[pr][o] = relu_f(acc);
        __syncthreads();
        acc = lb1[o];
        const float* h1 = hL1[pr];
        #pragma unroll 4
        for (int c = 0; c < 256; c++) acc += h1[c] * g_lw1t[c*256 + o];
        hL2[pr][o] = relu_f(acc);
        __syncthreads();
        acc = lb2[o];
        const float* h2 = hL2[pr];
        #pragma unroll 4
        for (int c = 0; c < 256; c++) acc += h2[c] * g_lw2t[c*256 + o];
        g_lf[(q0 + pr)*256 + o] = relu_f(acc);
    }
}

// ---------------- kernel D: FiLM + all outputs ---------------------------------------
// FiLM index collapse (verified): scale index d' = (d*P + p) mod D
//   D=128, P=256 -> d' = p % 128 ;  D=256, P=256 -> d' = p
__global__ void k_out(float* __restrict__ out, const float* __restrict__ xyz,
                      const int* __restrict__ inds) {
    const int O0 = BB*PP*3;           // 6144
    const int O1 = O0 + BB*128*PP;    // 268288
    const int O2 = O1 + BB*256*PP;    // 792576
    const int O3 = O2 + BB*PP;        // 794624
    int i = blockIdx.x * blockDim.x + threadIdx.x;
    if (i < O0) {
        int b = i / (PP*3); int r = i - b*(PP*3); int p = r/3, d = r - p*3;
        out[i] = xyz[((size_t)b*NN + inds[b*PP + p])*3 + d];
    } else if (i < O1) {
        int j = i - O0;
        int b = j >> 15;
        int r = j & 32767;
        int d = r >> 8, p = r & 255;
        int m = p & 127;
        out[i] = g_nf[((b<<8) + p)*128 + d] * (g_ss[b*256 + m] + 1.0f)
               + g_ss[b*256 + 128 + m];
    } else if (i < O2) {
        int j = i - O1;
        int b = j >> 16;
        int r = j & 65535;
        int d = r >> 8, p = r & 255;
        out[i] = g_lf[((b<<8) + p)*256 + d] * (g_ss2[b*512 + p] + 1.0f)
               + g_ss2[b*512 + 256 + p];
    } else if (i < O3) {
        out[i] = (float)inds[i - O2];
    }
}

// ---------------- launcher -----------------------------------------------------------
extern "C" void kernel_launch(void* const* d_in, const int* in_sizes, int n_in,
                              void* d_out, int out_size) {
    const float* xyz    = (const float*)d_in[0];
    const float* feat   = (const float*)d_in[1];
    const float* bsize  = (const float*)d_in[2];
    const float* blabel = (const float*)d_in[3];
    const float* ts     = (const float*)d_in[4];
    const int*   inds   = (const int*)  d_in[5];
    const float* mw0 = (const float*)d_in[6],  *mb0 = (const float*)d_in[7];
    const float* mw1 = (const float*)d_in[8],  *mb1 = (const float*)d_in[9];
    const float* mw2 = (const float*)d_in[10], *mb2 = (const float*)d_in[11];
    const float* lw0 = (const float*)d_in[12], *lb0 = (const float*)d_in[13];
    const float* lw1 = (const float*)d_in[14], *lb1 = (const float*)d_in[15];
    const float* lw2 = (const float*)d_in[16], *lb2 = (const float*)d_in[17];
    const float* tw0 = (const float*)d_in[18], *tb0 = (const float*)d_in[19];
    const float* tw1 = (const float*)d_in[20], *tb1 = (const float*)d_in[21];
    const float* bw  = (const float*)d_in[22], *bbv = (const float*)d_in[23];
    const float* tlw0= (const float*)d_in[24], *tlb0= (const float*)d_in[25];
    const float* tlw1= (const float*)d_in[26], *tlb1= (const float*)d_in[27];
    const float* blw = (const float*)d_in[28], *blb = (const float*)d_in[29];
    float* out = (float*)d_out;

    dim3 tb(32, 8);
    k_transpose_all<<<236, tb>>>(mw0, mw1, mw2, lw0, lw1, lw2);
    k_soa<<<(BB*NPAD + 255)/256, 256>>>(xyz);
    k_emb<<<BB, 128>>>(ts);
    k_sample<<<BP/2, 64>>>(xyz, bsize, inds);

    int smem_t = (8*(1024+4) + 32*132) * (int)sizeof(float);   // 49792 B
    cudaFuncSetAttribute(k_tstage, cudaFuncAttributeMaxDynamicSharedMemorySize, smem_t);
    k_tstage<<<48, 256, smem_t>>>(tw0, tb0, tlw0, tlb0, 512, 0);

    int smem_b = (259*64 + 128*OS) * (int)sizeof(float);       // 101120 B
    cudaFuncSetAttribute(k_mlp, cudaFuncAttributeMaxDynamicSharedMemorySize, smem_b);
    k_mlp<<<BP/2, 512, smem_b>>>(xyz, feat, inds, mb0, mb1, mb2,
                                 blabel, lb0, lb1, lb2);

    k_tstage<<<48, 256, smem_t>>>(tw1, tb1, tlw1, tlb1, 512, 1);
    k_tstage<<<24, 256, smem_t>>>(bw,  bbv, blw,  blb,  256, 2);

    const int total = BB*PP*3 + BB*128*PP + BB*256*PP + BB*PP;  // 794624
    k_out<<<(total + 255)/256, 256>>>(out, xyz, inds);
}

// round 10
// speedup vs baseline: 1.7868x; 1.0485x over previous
#include <cuda_runtime.h>
#include <math.h>

// Problem constants
#define BB   8
#define NN   20000
#define NPAD 20480        // 160 * 128 (multiple of 512 -> 4 warps x 40 float4-iters)
#define QTR  (NPAD/4)     // 5120 points per warp-quarter
#define PP   256
#define SS   32
#define CC   256
#define NCC  18
#define BP   (BB*PP)      // 2048

// ---------------- scratch (__device__ globals; no allocation allowed) ---------------
// NOTE: never pass these as kernel arguments from host code -- host-side symbol
// addresses are NOT device addresses (ATS makes the bug silent on GB300).
__device__ int   g_sel[BP*SS];
__device__ float g_nf [BP*128];
__device__ float g_lf [BP*256];
__device__ float g_ss [BB*256];
__device__ float g_ss2[BB*512];
__device__ __align__(16) float g_sx[BB*NPAD];
__device__ __align__(16) float g_sy[BB*NPAD];
__device__ __align__(16) float g_sz[BB*NPAD];
__device__ float g_e1[BB*128], g_e2[BB*256];
__device__ float g_t1[BB*512], g_t2[BB*1024];
__device__ float g_s1[BB*512], g_s2[BB*1024];

// transposed weights: layout [K][O] (wt[c*O + o]) -- point/label MLP weights only
__device__ __align__(16) float g_mw0t [259*128];
__device__ __align__(16) float g_mw1t [128*128];
__device__ __align__(16) float g_mw2t [128*128];
__device__ __align__(16) float g_lw0t [146*256];
__device__ __align__(16) float g_lw1t [256*256];
__device__ __align__(16) float g_lw2t [256*256];

// ---------------- activations --------------------------------------------------------
__device__ __forceinline__ float gelu_exact(float x) {
    return 0.5f * x * (1.0f + erff(x * 0.70710678118654752f));
}
__device__ __forceinline__ float silu_f(float x) { return x / (1.0f + expf(-x)); }
__device__ __forceinline__ float relu_f(float x) { return fmaxf(x, 0.0f); }

// ---------------- kernel T: fused tiled transpose of the 6 MLP weights --------------
__global__ void k_transpose_all(const float* __restrict__ mw0, const float* __restrict__ mw1,
                                const float* __restrict__ mw2, const float* __restrict__ lw0,
                                const float* __restrict__ lw1, const float* __restrict__ lw2) {
    int t = blockIdx.x;
    const float* src; float* dst; int O, K, base;
    if      (t < 36)  { src = mw0; dst = g_mw0t; O = 128; K = 259; base = 0;   }
    else if (t < 52)  { src = mw1; dst = g_mw1t; O = 128; K = 128; base = 36;  }
    else if (t < 68)  { src = mw2; dst = g_mw2t; O = 128; K = 128; base = 52;  }
    else if (t < 108) { src = lw0; dst = g_lw0t; O = 256; K = 146; base = 68;  }
    else if (t < 172) { src = lw1; dst = g_lw1t; O = 256; K = 256; base = 108; }
    else              { src = lw2; dst = g_lw2t; O = 256; K = 256; base = 172; }
    int tile = t - base;
    int ntk = (K + 31) >> 5;
    int kt = tile % ntk, ot = tile / ntk;
    __shared__ float s[32][33];
    int k0 = kt * 32, o0 = ot * 32;
    int tx = threadIdx.x, ty = threadIdx.y;   // 32 x 8
    #pragma unroll
    for (int i = ty; i < 32; i += 8) {
        int o = o0 + i, k = k0 + tx;
        if (o < O && k < K) s[i][tx] = src[o * K + k];
    }
    __syncthreads();
    #pragma unroll
    for (int i = ty; i < 32; i += 8) {
        int k = k0 + i, o = o0 + tx;
        if (k < K && o < O) dst[k * O + o] = s[tx][i];
    }
}

// ---------------- kernel S0: AoS -> SoA with sentinel padding ------------------------
__global__ void k_soa(const float* __restrict__ xyz) {
    int i = blockIdx.x * 256 + threadIdx.x;
    if (i >= BB * NPAD) return;
    int b = i / NPAD, n = i - b * NPAD;
    float x = 3e38f, y = 3e38f, z = 3e38f;
    if (n < NN) {
        const float* p = xyz + ((size_t)b * NN + n) * 3;
        x = p[0]; y = p[1]; z = p[2];
    }
    g_sx[i] = x; g_sy[i] = y; g_sz[i] = z;
}

// ---------------- kernel A: in-box sampling, 4 warps/proposal quarter-scan + merge --
// Warp w scans points [w*QTR, (w+1)*QTR), records its first <=32 hits in index order
// plus an exact count (exact whenever < 32 -- no early exit fired). A 32-thread merge
// concatenates quarters in index order; counts only matter when total < 32.
__global__ void __launch_bounds__(128) k_sample(const float* __restrict__ xyz,
                         const float* __restrict__ bsize,
                         const int*   __restrict__ inds) {
    __shared__ int buf[4][SS];
    __shared__ int cnt[4];
    int tid = threadIdx.x;
    int lane = tid & 31, w = tid >> 5;
    int q = blockIdx.x;
    int b = q >> 8;
    int n0 = inds[q];
    const float* cp = xyz + ((size_t)b * NN + n0) * 3;
    float cx = cp[0], cy = cp[1], cz = cp[2];
    float hx = bsize[q*3+0]*0.5f, hy = bsize[q*3+1]*0.5f, hz = bsize[q*3+2]*0.5f;
    const float4* X = (const float4*)(g_sx + b * NPAD);
    const float4* Y = (const float4*)(g_sy + b * NPAD);
    const float4* Z = (const float4*)(g_sz + b * NPAD);

    int vbase = w * (QTR/4);                       // float4 base for this quarter
    unsigned below = (1u << lane) - 1u;
    int found = 0;
    float4 xs = X[vbase + lane], ys = Y[vbase + lane], zs = Z[vbase + lane];
    const int ITERS = QTR / 128;                   // 40
    for (int it = 0; it < ITERS; it++) {
        float4 nx, ny, nz;
        if (it + 1 < ITERS) {                      // prefetch next chunk before ballots
            int v = vbase + (it + 1) * 32 + lane;
            nx = X[v]; ny = Y[v]; nz = Z[v];
        }
        bool i0 = (fabsf(xs.x-cx)<=hx) && (fabsf(ys.x-cy)<=hy) && (fabsf(zs.x-cz)<=hz);
        bool i1 = (fabsf(xs.y-cx)<=hx) && (fabsf(ys.y-cy)<=hy) && (fabsf(zs.y-cz)<=hz);
        bool i2 = (fabsf(xs.z-cx)<=hx) && (fabsf(ys.z-cy)<=hy) && (fabsf(zs.z-cz)<=hz);
        bool i3 = (fabsf(xs.w-cx)<=hx) && (fabsf(ys.w-cy)<=hy) && (fabsf(zs.w-cz)<=hz);
        unsigned m0 = __ballot_sync(0xffffffffu, i0);
        unsigned m1 = __ballot_sync(0xffffffffu, i1);
        unsigned m2 = __ballot_sync(0xffffffffu, i2);
        unsigned m3 = __ballot_sync(0xffffffffu, i3);
        if (m0 | m1 | m2 | m3) {
            int pre = found
                    + __popc(m0 & below) + __popc(m1 & below)
                    + __popc(m2 & below) + __popc(m3 & below);
            int np = w * QTR + it * 128 + 4 * lane;
            unsigned b0 = (m0 >> lane) & 1u, b1 = (m1 >> lane) & 1u, b2 = (m2 >> lane) & 1u;
            if (i0 && pre < SS)                    buf[w][pre] = np;
            int r1 = pre + (int)b0;
            if (i1 && r1 < SS)                     buf[w][r1] = np + 1;
            int r2 = r1 + (int)b1;
            if (i2 && r2 < SS)                     buf[w][r2] = np + 2;
            int r3 = r2 + (int)b2;
            if (i3 && r3 < SS)                     buf[w][r3] = np + 3;
        }
        found += __popc(m0) + __popc(m1) + __popc(m2) + __popc(m3);
        if (found >= SS) break;                    // warp-uniform
        xs = nx; ys = ny; zs = nz;
    }
    if (lane == 0) cnt[w] = found;
    __syncthreads();

    if (tid < 32) {
        int c0 = cnt[0], c1 = cnt[1], c2 = cnt[2], c3 = cnt[3];
        int s0 = c0 < SS ? c0 : SS;
        int s1 = c1 < SS ? c1 : SS;
        int s2 = c2 < SS ? c2 : SS;
        int total = c0 + c1 + c2 + c3;
        int eff = total < SS ? total : SS;
        int sel = 0;
        if (eff > 0) {
            int j = tid % eff;
            if (j < s0) sel = buf[0][j];
            else { j -= s0;
                if (j < s1) sel = buf[1][j];
                else { j -= s1;
                    if (j < s2) sel = buf[2][j];
                    else sel = buf[3][j - s2];
                }
            }
        }
        g_sel[q*SS + tid] = sel;
    }
}

// ---------------- time-MLP chain: embeddings + 3 GEMV stage kernels -----------------
__global__ void k_emb(const float* __restrict__ ts) {  // grid BB, block 128
    int b = blockIdx.x, tid = threadIdx.x;
    float t = ts[b];
    if (tid < 64) {
        float f = expf(tid * (-9.210340371976184f/63.0f));
        float e = t * f;
        g_e1[b*128 + tid] = sinf(e); g_e1[b*128 + 64 + tid] = cosf(e);
    }
    {
        float f = expf(tid * (-9.210340371976184f/127.0f));
        float e = t * f;
        g_e2[b*256 + tid] = sinf(e); g_e2[b*256 + 128 + tid] = cosf(e);
    }
}

// One block = 32 rows x 8 batches. Weights staged in smem, read once from L2/DRAM.
// Scratch in/out pointers resolved IN DEVICE CODE from `stage` (0,1,2) + side.
__global__ void k_tstage(const float* __restrict__ WA, const float* __restrict__ bA,
                         const float* __restrict__ WB, const float* __restrict__ bB,
                         int RA, int stage) {
    extern __shared__ float dsm[];
    int blk = blockIdx.x;
    int nA = RA >> 5;
    bool isA = blk < nA;
    const float *W = isA ? WA : WB;
    const float *bias = isA ? bA : bB;
    int row0 = (isA ? blk : blk - nA) << 5;
    const float* gin; float* gout; int K, R; int act;
    if (stage == 0) {
        act = 0;
        if (isA) { gin = g_e1; gout = g_t1; K = 128;  R = 512;  }
        else     { gin = g_e2; gout = g_t2; K = 256;  R = 1024; }
    } else if (stage == 1) {
        act = 1;
        if (isA) { gin = g_t1; gout = g_s1; K = 512;  R = 512;  }
        else     { gin = g_t2; gout = g_s2; K = 1024; R = 1024; }
    } else {
        act = 2;
        if (isA) { gin = g_s1; gout = g_ss;  K = 512;  R = 256; }
        else     { gin = g_s2; gout = g_ss2; K = 1024; R = 512; }
    }
    float* in_s = dsm;                 // [8][K+4]
    float* w_s  = dsm + 8 * (K + 4);   // [32][132]
    int tid = threadIdx.x;             // 256
    int rl = tid >> 3, bb = tid & 7;
    int stride = K + 4;
    int ksh = __ffs(K) - 1;            // K is a power of two (128..1024)
    for (int i = tid; i < (K << 3); i += 256) {
        int b2 = i >> ksh, c = i & (K - 1);
        in_s[b2 * stride + c] = gin[i];
    }
    float acc = 0.0f;
    for (int ko = 0; ko < K; ko += 128) {
        __syncthreads();
        #pragma unroll
        for (int i = tid; i < 1024; i += 256) {      // 32 rows x 128 cols as float4
            int r = i >> 5, c4 = i & 31;
            float4 v = *(const float4*)(W + (size_t)(row0 + r) * K + ko + c4 * 4);
            *(float4*)&w_s[r * 132 + c4 * 4] = v;
        }
        __syncthreads();
        const float* wr = w_s + rl * 132;
        const float* ir = in_s + bb * stride + ko;
        #pragma unroll 8
        for (int c = 0; c < 128; c++) acc += wr[c] * ir[c];
    }
    acc += bias[row0 + rl];
    if (act == 0) acc = gelu_exact(acc);
    else if (act == 1) acc = silu_f(acc);
    gout[bb * R + row0 + rl] = acc;
}

// ---------------- kernel B: register-tiled point MLP + maxpool + label MLP ----------
// Block = 2 proposals (64 points) x 128 outputs; 256 threads, 4pts x 8outs per thread.
// Per c-step per thread: 1 LDS.128 + 2 LDG.128 (half-warp-uniform) + 32 FFMA
//  -> smem crossbar at ~50% of the FFMA wall (was 2x over at 16 FFMA/LDS.128).
#define OS 68   // output row stride (floats)

template<int K, int IS>
__device__ __forceinline__ void layerT8(const float* __restrict__ in,
                                        const float* __restrict__ wt,
                                        const float* __restrict__ bias,
                                        float* __restrict__ out,
                                        int pg, int oh) {
    float4 acc[8];
    {
        float4 b0 = reinterpret_cast<const float4*>(bias)[2*oh];
        float4 b1 = reinterpret_cast<const float4*>(bias)[2*oh+1];
        acc[0] = make_float4(b0.x,b0.x,b0.x,b0.x);
        acc[1] = make_float4(b0.y,b0.y,b0.y,b0.y);
        acc[2] = make_float4(b0.z,b0.z,b0.z,b0.z);
        acc[3] = make_float4(b0.w,b0.w,b0.w,b0.w);
        acc[4] = make_float4(b1.x,b1.x,b1.x,b1.x);
        acc[5] = make_float4(b1.y,b1.y,b1.y,b1.y);
        acc[6] = make_float4(b1.z,b1.z,b1.z,b1.z);
        acc[7] = make_float4(b1.w,b1.w,b1.w,b1.w);
    }
    const float* ip = in + 4*pg;
    const float* wp = wt + 8*oh;
    #pragma unroll 2
    for (int c = 0; c < K; c++) {
        float4 x = *(const float4*)(ip + c*IS);
        float ws[8];
        *(float4*)&ws[0] = *(const float4*)(wp + c*128);
        *(float4*)&ws[4] = *(const float4*)(wp + c*128 + 4);
        #pragma unroll
        for (int j = 0; j < 8; j++) {
            acc[j].x += x.x*ws[j]; acc[j].y += x.y*ws[j];
            acc[j].z += x.z*ws[j]; acc[j].w += x.w*ws[j];
        }
    }
    float* o = out + 4*pg;
    #pragma unroll
    for (int j = 0; j < 8; j++) {
        *(float4*)(o + (8*oh + j)*OS) =
            make_float4(relu_f(acc[j].x), relu_f(acc[j].y),
                        relu_f(acc[j].z), relu_f(acc[j].w));
    }
}

__global__ void __launch_bounds__(256, 2) k_mlp(
                      const float* __restrict__ xyz, const float* __restrict__ feat,
                      const int* __restrict__ inds,
                      const float* __restrict__ mb0, const float* __restrict__ mb1,
                      const float* __restrict__ mb2,
                      const float* __restrict__ blabel,
                      const float* __restrict__ lb0, const float* __restrict__ lb1,
                      const float* __restrict__ lb2) {
    extern __shared__ float sm[];
    float* g  = sm;                     // [259][64] layer0 input; reused as hB [128][OS]
    float* hA = sm + 259*64;            // [128][OS]
    __shared__ int   sidx[64];
    __shared__ float ctr[2][3];
    __shared__ float in0[2][152];
    __shared__ float hL1[2][256], hL2[2][256];

    int q0 = blockIdx.x * 2, b = q0 >> 8;    // both proposals in same batch (PP even)
    int tid = threadIdx.x;                   // 256 threads
    if (tid < 64) sidx[tid] = g_sel[(q0 + (tid >> 5))*SS + (tid & 31)];
    if (tid < 6) {
        int pr = tid / 3, d = tid - pr*3;
        int n0 = inds[q0 + pr];
        ctr[pr][d] = xyz[((size_t)b*NN + n0)*3 + d];
    }
    if (tid < 2*NCC) {
        int pr = tid / NCC, c = tid - pr*NCC;
        in0[pr][c] = blabel[(q0 + pr)*NCC + c];
    }
    __syncthreads();

    // gather: g[3+c][s] = feat[b][c][sidx[s]] ; g[d][s] = xyz - ctr
    const float* fb = feat + (size_t)b * CC * NN;
    for (int i = tid; i < 64 * CC; i += 256) {
        int s = i & 63, c = i >> 6;
        g[(3 + c)*64 + s] = __ldg(fb + (size_t)c * NN + sidx[s]);
    }
    if (tid < 192) {
        int s = tid & 63, d = tid >> 6, pr = s >> 5;
        g[d*64 + s] = xyz[((size_t)b*NN + sidx[s])*3 + d] - ctr[pr][d];
    }
    __syncthreads();

    int pg = tid & 15, oh = tid >> 4;       // pg in [0,16), oh in [0,16)
    layerT8<259, 64>(g,  g_mw0t, mb0, hA, pg, oh); __syncthreads();
    layerT8<128, OS>(hA, g_mw1t, mb1, g,  pg, oh); __syncthreads();
    layerT8<128, OS>(g,  g_mw2t, mb2, hA, pg, oh); __syncthreads();

    // maxpool over 32 samples per proposal (relu outputs >= 0)
    {
        int o = tid & 127, pr = tid >> 7;
        const float* r = hA + o*OS + pr*32;
        float m = 0.0f;
        #pragma unroll
        for (int j = 0; j < 32; j += 4) {
            float4 v = *(const float4*)(r + j);
            m = fmaxf(m, fmaxf(fmaxf(v.x, v.y), fmaxf(v.z, v.w)));
        }
        g_nf[(q0 + pr)*128 + o] = m;
        in0[pr][NCC + o] = m;
    }
    __syncthreads();

    // fused label MLP: 146 -> 256 -> 256 -> 256; thread = output o, both proposals
    {
        int o = tid;
        float a0 = lb0[o], a1 = a0;
        #pragma unroll 2
        for (int c = 0; c < 146; c++) {
            float wv = g_lw0t[c*256 + o];
            a0 += in0[0][c] * wv; a1 += in0[1][c] * wv;
        }
        hL1[0][o] = relu_f(a0); hL1[1][o] = relu_f(a1);
        __syncthreads();
        a0 = lb1[o]; a1 = a0;
        #pragma unroll 4
        for (int c = 0; c < 256; c++) {
            float wv = g_lw1t[c*256 + o];
            a0 += hL1[0][c] * wv; a1 += hL1[1][c] * wv;
        }
        hL2[0][o] = relu_f(a0); hL2[1][o] = relu_f(a1);
        __syncthreads();
        a0 = lb2[o]; a1 = a0;
        #pragma unroll 4
        for (int c = 0; c < 256; c++) {
            float wv = g_lw2t[c*256 + o];
            a0 += hL2[0][c] * wv; a1 += hL2[1][c] * wv;
        }
        g_lf[q0*256 + o]       = relu_f(a0);
        g_lf[(q0 + 1)*256 + o] = relu_f(a1);
    }
}

// ---------------- kernel D: FiLM + all outputs ---------------------------------------
// FiLM index collapse (verified): scale index d' = (d*P + p) mod D
//   D=128, P=256 -> d' = p % 128 ;  D=256, P=256 -> d' = p
__global__ void k_out(float* __restrict__ out, const float* __restrict__ xyz,
                      const int* __restrict__ inds) {
    const int O0 = BB*PP*3;           // 6144
    const int O1 = O0 + BB*128*PP;    // 268288
    const int O2 = O1 + BB*256*PP;    // 792576
    const int O3 = O2 + BB*PP;        // 794624
    int i = blockIdx.x * blockDim.x + threadIdx.x;
    if (i < O0) {
        int b = i / (PP*3); int r = i - b*(PP*3); int p = r/3, d = r - p*3;
        out[i] = xyz[((size_t)b*NN + inds[b*PP + p])*3 + d];
    } else if (i < O1) {
        int j = i - O0;
        int b = j >> 15;
        int r = j & 32767;
        int d = r >> 8, p = r & 255;
        int m = p & 127;
        out[i] = g_nf[((b<<8) + p)*128 + d] * (g_ss[b*256 + m] + 1.0f)
               + g_ss[b*256 + 128 + m];
    } else if (i < O2) {
        int j = i - O1;
        int b = j >> 16;
        int r = j & 65535;
        int d = r >> 8, p = r & 255;
        out[i] = g_lf[((b<<8) + p)*256 + d] * (g_ss2[b*512 + p] + 1.0f)
               + g_ss2[b*512 + 256 + p];
    } else if (i < O3) {
        out[i] = (float)inds[i - O2];
    }
}

// ---------------- launcher -----------------------------------------------------------
extern "C" void kernel_launch(void* const* d_in, const int* in_sizes, int n_in,
                              void* d_out, int out_size) {
    const float* xyz    = (const float*)d_in[0];
    const float* feat   = (const float*)d_in[1];
    const float* bsize  = (const float*)d_in[2];
    const float* blabel = (const float*)d_in[3];
    const float* ts     = (const float*)d_in[4];
    const int*   inds   = (const int*)  d_in[5];
    const float* mw0 = (const float*)d_in[6],  *mb0 = (const float*)d_in[7];
    const float* mw1 = (const float*)d_in[8],  *mb1 = (const float*)d_in[9];
    const float* mw2 = (const float*)d_in[10], *mb2 = (const float*)d_in[11];
    const float* lw0 = (const float*)d_in[12], *lb0 = (const float*)d_in[13];
    const float* lw1 = (const float*)d_in[14], *lb1 = (const float*)d_in[15];
    const float* lw2 = (const float*)d_in[16], *lb2 = (const float*)d_in[17];
    const float* tw0 = (const float*)d_in[18], *tb0 = (const float*)d_in[19];
    const float* tw1 = (const float*)d_in[20], *tb1 = (const float*)d_in[21];
    const float* bw  = (const float*)d_in[22], *bbv = (const float*)d_in[23];
    const float* tlw0= (const float*)d_in[24], *tlb0= (const float*)d_in[25];
    const float* tlw1= (const float*)d_in[26], *tlb1= (const float*)d_in[27];
    const float* blw = (const float*)d_in[28], *blb = (const float*)d_in[29];
    float* out = (float*)d_out;

    dim3 tb(32, 8);
    k_transpose_all<<<236, tb>>>(mw0, mw1, mw2, lw0, lw1, lw2);
    k_soa<<<(BB*NPAD + 255)/256, 256>>>(xyz);
    k_emb<<<BB, 128>>>(ts);
    k_sample<<<BP, 128>>>(xyz, bsize, inds);

    int smem_t = (8*(1024+4) + 32*132) * (int)sizeof(float);   // 49792 B
    cudaFuncSetAttribute(k_tstage, cudaFuncAttributeMaxDynamicSharedMemorySize, smem_t);
    k_tstage<<<48, 256, smem_t>>>(tw0, tb0, tlw0, tlb0, 512, 0);

    int smem_b = (259*64 + 128*OS) * (int)sizeof(float);       // 101120 B
    cudaFuncSetAttribute(k_mlp, cudaFuncAttributeMaxDynamicSharedMemorySize, smem_b);
    k_mlp<<<BP/2, 256, smem_b>>>(xyz, feat, inds, mb0, mb1, mb2,
                                 blabel, lb0, lb1, lb2);

    k_tstage<<<48, 256, smem_t>>>(tw1, tb1, tlw1, tlb1, 512, 1);
    k_tstage<<<24, 256, smem_t>>>(bw,  bbv, blw,  blb,  256, 2);

    const int total = BB*PP*3 + BB*128*PP + BB*256*PP + BB*PP;  // 794624
    k_out<<<(total + 255)/256, 256>>>(out, xyz, inds);
}

// round 11
// speedup vs baseline: 1.8580x; 1.0399x over previous
#include <cuda_runtime.h>
#include <math.h>

// Problem constants
#define BB   8
#define NN   20000
#define NPAD 20480        // 160 * 128 (multiple of 512 -> 4 warps x 40 float4-iters)
#define QTR  (NPAD/4)     // 5120 points per warp-quarter
#define PP   256
#define SS   32
#define CC   256
#define NCC  18
#define BP   (BB*PP)      // 2048
#define STR0 264          // point-major gather row stride (floats)
#define OS   68           // channel-major hidden row stride (floats)

// ---------------- scratch (__device__ globals; no allocation allowed) ---------------
// NOTE: never pass these as kernel arguments from host code -- host-side symbol
// addresses are NOT device addresses (ATS makes the bug silent on GB300).
__device__ int   g_sel[BP*SS];
__device__ float g_nf [BP*128];
__device__ float g_lf [BP*256];
__device__ float g_ss [BB*256];
__device__ float g_ss2[BB*512];
__device__ __align__(16) float g_sx[BB*NPAD];
__device__ __align__(16) float g_sy[BB*NPAD];
__device__ __align__(16) float g_sz[BB*NPAD];
__device__ __align__(16) float g_ft[(size_t)BB*NN*CC];   // features transposed [b][n][c]
__device__ float g_e1[BB*128], g_e2[BB*256];
__device__ float g_t1[BB*512], g_t2[BB*1024];
__device__ float g_s1[BB*512], g_s2[BB*1024];

// transposed weights: layout [K][O] (wt[c*O + o]) -- point/label MLP weights only
// g_mw0t rows are PERMUTED: row c<256 = feature channel c (orig col 3+c);
//                           rows 256..258 = xyz (orig cols 0..2)
__device__ __align__(16) float g_mw0t [259*128];
__device__ __align__(16) float g_mw1t [128*128];
__device__ __align__(16) float g_mw2t [128*128];
__device__ __align__(16) float g_lw0t [146*256];
__device__ __align__(16) float g_lw1t [256*256];
__device__ __align__(16) float g_lw2t [256*256];

// ---------------- activations --------------------------------------------------------
__device__ __forceinline__ float gelu_exact(float x) {
    return 0.5f * x * (1.0f + erff(x * 0.70710678118654752f));
}
__device__ __forceinline__ float silu_f(float x) { return x / (1.0f + expf(-x)); }
__device__ __forceinline__ float relu_f(float x) { return fmaxf(x, 0.0f); }

// ---------------- kernel P: fused prep = xyz SoA + 6 weight transposes --------------
// blocks 0..639: SoA; blocks 640..875: 236 transpose tiles. blockDim = (32,8).
__global__ void k_prep(const float* __restrict__ xyz,
                       const float* __restrict__ mw0, const float* __restrict__ mw1,
                       const float* __restrict__ mw2, const float* __restrict__ lw0,
                       const float* __restrict__ lw1, const float* __restrict__ lw2) {
    int blk = blockIdx.x;
    int tx = threadIdx.x, ty = threadIdx.y;
    int tid = ty * 32 + tx;
    if (blk < 640) {                                // SoA with sentinel padding
        int i = blk * 256 + tid;
        if (i >= BB * NPAD) return;
        int b = i / NPAD, n = i - b * NPAD;
        float x = 3e38f, y = 3e38f, z = 3e38f;
        if (n < NN) {
            const float* p = xyz + ((size_t)b * NN + n) * 3;
            x = p[0]; y = p[1]; z = p[2];
        }
        g_sx[i] = x; g_sy[i] = y; g_sz[i] = z;
        return;
    }
    int t = blk - 640;
    const float* src; float* dst; int O, K, base; bool perm = false;
    if      (t < 36)  { src = mw0; dst = g_mw0t; O = 128; K = 259; base = 0;   perm = true; }
    else if (t < 52)  { src = mw1; dst = g_mw1t; O = 128; K = 128; base = 36;  }
    else if (t < 68)  { src = mw2; dst = g_mw2t; O = 128; K = 128; base = 52;  }
    else if (t < 108) { src = lw0; dst = g_lw0t; O = 256; K = 146; base = 68;  }
    else if (t < 172) { src = lw1; dst = g_lw1t; O = 256; K = 256; base = 108; }
    else              { src = lw2; dst = g_lw2t; O = 256; K = 256; base = 172; }
    int tile = t - base;
    int ntk = (K + 31) >> 5;
    int kt = tile % ntk, ot = tile / ntk;
    __shared__ float s[32][33];
    int k0 = kt * 32, o0 = ot * 32;
    #pragma unroll
    for (int i = ty; i < 32; i += 8) {
        int o = o0 + i, k = k0 + tx;
        if (o < O && k < K) {
            int sk = perm ? (k < 256 ? k + 3 : k - 256) : k;
            s[i][tx] = src[o * K + sk];
        }
    }
    __syncthreads();
    #pragma unroll
    for (int i = ty; i < 32; i += 8) {
        int k = k0 + i, o = o0 + tx;
        if (k < K && o < O) dst[k * O + o] = s[tx][i];
    }
}

// ---------------- kernel F: feature transpose [C][N] -> [N][C] ----------------------
// grid (625, 8, 8) = (n-tile, c-tile, b); 625*32 = 20000 exactly.
__global__ void k_ftrans(const float* __restrict__ feat) {
    __shared__ float t[32][33];
    int tx = threadIdx.x, ty = threadIdx.y;       // 32 x 8
    int n0 = blockIdx.x << 5, c0 = blockIdx.y << 5, b = blockIdx.z;
    const float* src = feat + ((size_t)(b * CC + c0)) * NN + n0;
    #pragma unroll
    for (int i = ty; i < 32; i += 8)
        t[i][tx] = src[(size_t)i * NN + tx];
    __syncthreads();
    float* dst = g_ft + ((size_t)b * NN + n0) * CC + c0;
    #pragma unroll
    for (int i = ty; i < 32; i += 8)
        dst[(size_t)i * CC + tx] = t[tx][i];
}

// ---------------- kernel A: in-box sampling, 4 warps/proposal quarter-scan + merge --
__global__ void __launch_bounds__(128) k_sample(const float* __restrict__ xyz,
                         const float* __restrict__ bsize,
                         const int*   __restrict__ inds) {
    __shared__ int buf[4][SS];
    __shared__ int cnt[4];
    int tid = threadIdx.x;
    int lane = tid & 31, w = tid >> 5;
    int q = blockIdx.x;
    int b = q >> 8;
    int n0 = inds[q];
    const float* cp = xyz + ((size_t)b * NN + n0) * 3;
    float cx = cp[0], cy = cp[1], cz = cp[2];
    float hx = bsize[q*3+0]*0.5f, hy = bsize[q*3+1]*0.5f, hz = bsize[q*3+2]*0.5f;
    const float4* X = (const float4*)(g_sx + b * NPAD);
    const float4* Y = (const float4*)(g_sy + b * NPAD);
    const float4* Z = (const float4*)(g_sz + b * NPAD);

    int vbase = w * (QTR/4);
    unsigned below = (1u << lane) - 1u;
    int found = 0;
    float4 xs = X[vbase + lane], ys = Y[vbase + lane], zs = Z[vbase + lane];
    const int ITERS = QTR / 128;                   // 40
    for (int it = 0; it < ITERS; it++) {
        float4 nx, ny, nz;
        if (it + 1 < ITERS) {
            int v = vbase + (it + 1) * 32 + lane;
            nx = X[v]; ny = Y[v]; nz = Z[v];
        }
        bool i0 = (fabsf(xs.x-cx)<=hx) && (fabsf(ys.x-cy)<=hy) && (fabsf(zs.x-cz)<=hz);
        bool i1 = (fabsf(xs.y-cx)<=hx) && (fabsf(ys.y-cy)<=hy) && (fabsf(zs.y-cz)<=hz);
        bool i2 = (fabsf(xs.z-cx)<=hx) && (fabsf(ys.z-cy)<=hy) && (fabsf(zs.z-cz)<=hz);
        bool i3 = (fabsf(xs.w-cx)<=hx) && (fabsf(ys.w-cy)<=hy) && (fabsf(zs.w-cz)<=hz);
        unsigned m0 = __ballot_sync(0xffffffffu, i0);
        unsigned m1 = __ballot_sync(0xffffffffu, i1);
        unsigned m2 = __ballot_sync(0xffffffffu, i2);
        unsigned m3 = __ballot_sync(0xffffffffu, i3);
        if (m0 | m1 | m2 | m3) {
            int pre = found
                    + __popc(m0 & below) + __popc(m1 & below)
                    + __popc(m2 & below) + __popc(m3 & below);
            int np = w * QTR + it * 128 + 4 * lane;
            unsigned b0 = (m0 >> lane) & 1u, b1 = (m1 >> lane) & 1u, b2 = (m2 >> lane) & 1u;
            if (i0 && pre < SS)                    buf[w][pre] = np;
            int r1 = pre + (int)b0;
            if (i1 && r1 < SS)                     buf[w][r1] = np + 1;
            int r2 = r1 + (int)b1;
            if (i2 && r2 < SS)                     buf[w][r2] = np + 2;
            int r3 = r2 + (int)b2;
            if (i3 && r3 < SS)                     buf[w][r3] = np + 3;
        }
        found += __popc(m0) + __popc(m1) + __popc(m2) + __popc(m3);
        if (found >= SS) break;
        xs = nx; ys = ny; zs = nz;
    }
    if (lane == 0) cnt[w] = found;
    __syncthreads();

    if (tid < 32) {
        int c0 = cnt[0], c1 = cnt[1], c2 = cnt[2], c3 = cnt[3];
        int s0 = c0 < SS ? c0 : SS;
        int s1 = c1 < SS ? c1 : SS;
        int s2 = c2 < SS ? c2 : SS;
        int total = c0 + c1 + c2 + c3;
        int eff = total < SS ? total : SS;
        int sel = 0;
        if (eff > 0) {
            int j = tid % eff;
            if (j < s0) sel = buf[0][j];
            else { j -= s0;
                if (j < s1) sel = buf[1][j];
                else { j -= s1;
                    if (j < s2) sel = buf[2][j];
                    else sel = buf[3][j - s2];
                }
            }
        }
        g_sel[q*SS + tid] = sel;
    }
}

// ---------------- time-MLP chain: embeddings + 3 GEMV stage kernels -----------------
__global__ void k_emb(const float* __restrict__ ts) {
    int b = blockIdx.x, tid = threadIdx.x;
    float t = ts[b];
    if (tid < 64) {
        float f = expf(tid * (-9.210340371976184f/63.0f));
        float e = t * f;
        g_e1[b*128 + tid] = sinf(e); g_e1[b*128 + 64 + tid] = cosf(e);
    }
    {
        float f = expf(tid * (-9.210340371976184f/127.0f));
        float e = t * f;
        g_e2[b*256 + tid] = sinf(e); g_e2[b*256 + 128 + tid] = cosf(e);
    }
}

__global__ void k_tstage(const float* __restrict__ WA, const float* __restrict__ bA,
                         const float* __restrict__ WB, const float* __restrict__ bB,
                         int RA, int stage) {
    extern __shared__ float dsm[];
    int blk = blockIdx.x;
    int nA = RA >> 5;
    bool isA = blk < nA;
    const float *W = isA ? WA : WB;
    const float *bias = isA ? bA : bB;
    int row0 = (isA ? blk : blk - nA) << 5;
    const float* gin; float* gout; int K, R; int act;
    if (stage == 0) {
        act = 0;
        if (isA) { gin = g_e1; gout = g_t1; K = 128;  R = 512;  }
        else     { gin = g_e2; gout = g_t2; K = 256;  R = 1024; }
    } else if (stage == 1) {
        act = 1;
        if (isA) { gin = g_t1; gout = g_s1; K = 512;  R = 512;  }
        else     { gin = g_t2; gout = g_s2; K = 1024; R = 1024; }
    } else {
        act = 2;
        if (isA) { gin = g_s1; gout = g_ss;  K = 512;  R = 256; }
        else     { gin = g_s2; gout = g_ss2; K = 1024; R = 512; }
    }
    float* in_s = dsm;
    float* w_s  = dsm + 8 * (K + 4);
    int tid = threadIdx.x;
    int rl = tid >> 3, bb = tid & 7;
    int stride = K + 4;
    int ksh = __ffs(K) - 1;
    for (int i = tid; i < (K << 3); i += 256) {
        int b2 = i >> ksh, c = i & (K - 1);
        in_s[b2 * stride + c] = gin[i];
    }
    float acc = 0.0f;
    for (int ko = 0; ko < K; ko += 128) {
        __syncthreads();
        #pragma unroll
        for (int i = tid; i < 1024; i += 256) {
            int r = i >> 5, c4 = i & 31;
            float4 v = *(const float4*)(W + (size_t)(row0 + r) * K + ko + c4 * 4);
            *(float4*)&w_s[r * 132 + c4 * 4] = v;
        }
        __syncthreads();
        const float* wr = w_s + rl * 132;
        const float* ir = in_s + bb * stride + ko;
        #pragma unroll 8
        for (int c = 0; c < 128; c++) acc += wr[c] * ir[c];
    }
    acc += bias[row0 + rl];
    if (act == 0) acc = gelu_exact(acc);
    else if (act == 1) acc = silu_f(acc);
    gout[bb * R + row0 + rl] = acc;
}

// ---------------- kernel B: coalesced gather + point MLP + maxpool + label MLP ------
// Layer0 input: point-major gpm[s][STR0] with 16B-chunk XOR swizzle (chunk ^ (s>>2)&7)
// on channels 0..255; xyz at columns 256..258 (weight rows permuted in k_prep).
// Layers 1-2: channel-major [128][OS] via layerT8.

template<int K, int IS>
__device__ __forceinline__ void layerT8(const float* __restrict__ in,
                                        const float* __restrict__ wt,
                                        const float* __restrict__ bias,
                                        float* __restrict__ out,
                                        int pg, int oh) {
    float4 acc[8];
    {
        float4 b0 = reinterpret_cast<const float4*>(bias)[2*oh];
        float4 b1 = reinterpret_cast<const float4*>(bias)[2*oh+1];
        acc[0] = make_float4(b0.x,b0.x,b0.x,b0.x);
        acc[1] = make_float4(b0.y,b0.y,b0.y,b0.y);
        acc[2] = make_float4(b0.z,b0.z,b0.z,b0.z);
        acc[3] = make_float4(b0.w,b0.w,b0.w,b0.w);
        acc[4] = make_float4(b1.x,b1.x,b1.x,b1.x);
        acc[5] = make_float4(b1.y,b1.y,b1.y,b1.y);
        acc[6] = make_float4(b1.z,b1.z,b1.z,b1.z);
        acc[7] = make_float4(b1.w,b1.w,b1.w,b1.w);
    }
    const float* ip = in + 4*pg;
    const float* wp = wt + 8*oh;
    #pragma unroll 2
    for (int c = 0; c < K; c++) {
        float4 x = *(const float4*)(ip + c*IS);
        float ws[8];
        *(float4*)&ws[0] = *(const float4*)(wp + c*128);
        *(float4*)&ws[4] = *(const float4*)(wp + c*128 + 4);
        #pragma unroll
        for (int j = 0; j < 8; j++) {
            acc[j].x += x.x*ws[j]; acc[j].y += x.y*ws[j];
            acc[j].z += x.z*ws[j]; acc[j].w += x.w*ws[j];
        }
    }
    float* o = out + 4*pg;
    #pragma unroll
    for (int j = 0; j < 8; j++) {
        *(float4*)(o + (8*oh + j)*OS) =
            make_float4(relu_f(acc[j].x), relu_f(acc[j].y),
                        relu_f(acc[j].z), relu_f(acc[j].w));
    }
}

__device__ __forceinline__ void layerPM(const float* __restrict__ in,  // gpm
                                        const float* __restrict__ wt,  // g_mw0t (permuted)
                                        const float* __restrict__ bias,
                                        float* __restrict__ out,
                                        int pg, int oh) {
    float4 acc[8];
    {
        float4 b0 = reinterpret_cast<const float4*>(bias)[2*oh];
        float4 b1 = reinterpret_cast<const float4*>(bias)[2*oh+1];
        acc[0] = make_float4(b0.x,b0.x,b0.x,b0.x);
        acc[1] = make_float4(b0.y,b0.y,b0.y,b0.y);
        acc[2] = make_float4(b0.z,b0.z,b0.z,b0.z);
        acc[3] = make_float4(b0.w,b0.w,b0.w,b0.w);
        acc[4] = make_float4(b1.x,b1.x,b1.x,b1.x);
        acc[5] = make_float4(b1.y,b1.y,b1.y,b1.y);
        acc[6] = make_float4(b1.z,b1.z,b1.z,b1.z);
        acc[7] = make_float4(b1.w,b1.w,b1.w,b1.w);
    }
    const float* ip0 = in + (4*pg+0)*STR0;
    const float* ip1 = in + (4*pg+1)*STR0;
    const float* ip2 = in + (4*pg+2)*STR0;
    const float* ip3 = in + (4*pg+3)*STR0;
    int P = pg & 7;
    const float* wp = wt + 8*oh;
    #pragma unroll 2
    for (int c = 0; c < 256; c++) {
        int t = ((((c >> 2) ^ P) << 2) | (c & 3));
        float x0 = ip0[t], x1 = ip1[t], x2 = ip2[t], x3 = ip3[t];
        float ws[8];
        *(float4*)&ws[0] = *(const float4*)(wp + c*128);
        *(float4*)&ws[4] = *(const float4*)(wp + c*128 + 4);
        #pragma unroll
        for (int j = 0; j < 8; j++) {
            acc[j].x += x0*ws[j]; acc[j].y += x1*ws[j];
            acc[j].z += x2*ws[j]; acc[j].w += x3*ws[j];
        }
    }
    #pragma unroll
    for (int c = 256; c < 259; c++) {                 // xyz, unswizzled
        float x0 = ip0[c], x1 = ip1[c], x2 = ip2[c], x3 = ip3[c];
        float ws[8];
        *(float4*)&ws[0] = *(const float4*)(wp + c*128);
        *(float4*)&ws[4] = *(const float4*)(wp + c*128 + 4);
        #pragma unroll
        for (int j = 0; j < 8; j++) {
            acc[j].x += x0*ws[j]; acc[j].y += x1*ws[j];
            acc[j].z += x2*ws[j]; acc[j].w += x3*ws[j];
        }
    }
    float* o = out + 4*pg;
    #pragma unroll
    for (int j = 0; j < 8; j++) {
        *(float4*)(o + (8*oh + j)*OS) =
            make_float4(relu_f(acc[j].x), relu_f(acc[j].y),
                        relu_f(acc[j].z), relu_f(acc[j].w));
    }
}

__global__ void __launch_bounds__(256, 2) k_mlp(
                      const float* __restrict__ xyz,
                      const int* __restrict__ inds,
                      const float* __restrict__ mb0, const float* __restrict__ mb1,
                      const float* __restrict__ mb2,
                      const float* __restrict__ blabel,
                      const float* __restrict__ lb0, const float* __restrict__ lb1,
                      const float* __restrict__ lb2) {
    extern __shared__ float sm[];
    float* gpm = sm;                    // [64][STR0] gather; reused as hB [128][OS]
    float* hA  = sm + 64*STR0;          // [128][OS]
    __shared__ int   sidx[64];
    __shared__ float ctr[2][3];
    __shared__ float in0[2][152];
    __shared__ float hL1[2][256], hL2[2][256];

    int q0 = blockIdx.x * 2, b = q0 >> 8;
    int tid = threadIdx.x;              // 256 threads
    if (tid < 64) sidx[tid] = g_sel[(q0 + (tid >> 5))*SS + (tid & 31)];
    if (tid < 6) {
        int pr = tid / 3, d = tid - pr*3;
        int n0 = inds[q0 + pr];
        ctr[pr][d] = xyz[((size_t)b*NN + n0)*3 + d];
    }
    if (tid < 2*NCC) {
        int pr = tid / NCC, c = tid - pr*NCC;
        in0[pr][c] = blabel[(q0 + pr)*NCC + c];
    }
    __syncthreads();

    // gather: 64 points x 64 float4 chunks, coalesced rows from g_ft, swizzled STS.128
    const float* ftb = g_ft + (size_t)b * NN * CC;
    #pragma unroll 4
    for (int i = tid; i < 64*64; i += 256) {
        int s = i >> 6, c4 = i & 63;
        float4 v = *(const float4*)(ftb + (size_t)sidx[s]*CC + (c4 << 2));
        int cc = c4 ^ ((s >> 2) & 7);
        *(float4*)(gpm + s*STR0 + (cc << 2)) = v;
    }
    if (tid < 192) {
        int s = tid & 63, d = tid >> 6, pr = s >> 5;
        gpm[s*STR0 + 256 + d] = xyz[((size_t)b*NN + sidx[s])*3 + d] - ctr[pr][d];
    }
    __syncthreads();

    int pg = tid & 15, oh = tid >> 4;
    layerPM(gpm, g_mw0t, mb0, hA, pg, oh);           __syncthreads();
    layerT8<128, OS>(hA, g_mw1t, mb1, gpm, pg, oh);  __syncthreads();
    layerT8<128, OS>(gpm, g_mw2t, mb2, hA, pg, oh);  __syncthreads();

    // maxpool over 32 samples per proposal (relu outputs >= 0)
    {
        int o = tid & 127, pr = tid >> 7;
        const float* r = hA + o*OS + pr*32;
        float m = 0.0f;
        #pragma unroll
        for (int j = 0; j < 32; j += 4) {
            float4 v = *(const float4*)(r + j);
            m = fmaxf(m, fmaxf(fmaxf(v.x, v.y), fmaxf(v.z, v.w)));
        }
        g_nf[(q0 + pr)*128 + o] = m;
        in0[pr][NCC + o] = m;
    }
    __syncthreads();

    // fused label MLP: 146 -> 256 -> 256 -> 256; thread = output o, both proposals
    {
        int o = tid;
        float a0 = lb0[o], a1 = a0;
        #pragma unroll 2
        for (int c = 0; c < 146; c++) {
            float wv = g_lw0t[c*256 + o];
            a0 += in0[0][c] * wv; a1 += in0[1][c] * wv;
        }
        hL1[0][o] = relu_f(a0); hL1[1][o] = relu_f(a1);
        __syncthreads();
        a0 = lb1[o]; a1 = a0;
        #pragma unroll 4
        for (int c = 0; c < 256; c++) {
            float wv = g_lw1t[c*256 + o];
            a0 += hL1[0][c] * wv; a1 += hL1[1][c] * wv;
        }
        hL2[0][o] = relu_f(a0); hL2[1][o] = relu_f(a1);
        __syncthreads();
        a0 = lb2[o]; a1 = a0;
        #pragma unroll 4
        for (int c = 0; c < 256; c++) {
            float wv = g_lw2t[c*256 + o];
            a0 += hL2[0][c] * wv; a1 += hL2[1][c] * wv;
        }
        g_lf[q0*256 + o]       = relu_f(a0);
        g_lf[(q0 + 1)*256 + o] = relu_f(a1);
    }
}

// ---------------- kernel D: FiLM + all outputs ---------------------------------------
__global__ void k_out(float* __restrict__ out, const float* __restrict__ xyz,
                      const int* __restrict__ inds) {
    const int O0 = BB*PP*3;           // 6144
    const int O1 = O0 + BB*128*PP;    // 268288
    const int O2 = O1 + BB*256*PP;    // 792576
    const int O3 = O2 + BB*PP;        // 794624
    int i = blockIdx.x * blockDim.x + threadIdx.x;
    if (i < O0) {
        int b = i / (PP*3); int r = i - b*(PP*3); int p = r/3, d = r - p*3;
        out[i] = xyz[((size_t)b*NN + inds[b*PP + p])*3 + d];
    } else if (i < O1) {
        int j = i - O0;
        int b = j >> 15;
        int r = j & 32767;
        int d = r >> 8, p = r & 255;
        int m = p & 127;
        out[i] = g_nf[((b<<8) + p)*128 + d] * (g_ss[b*256 + m] + 1.0f)
               + g_ss[b*256 + 128 + m];
    } else if (i < O2) {
        int j = i - O1;
        int b = j >> 16;
        int r = j & 65535;
        int d = r >> 8, p = r & 255;
        out[i] = g_lf[((b<<8) + p)*256 + d] * (g_ss2[b*512 + p] + 1.0f)
               + g_ss2[b*512 + 256 + p];
    } else if (i < O3) {
        out[i] = (float)inds[i - O2];
    }
}

// ---------------- launcher -----------------------------------------------------------
extern "C" void kernel_launch(void* const* d_in, const int* in_sizes, int n_in,
                              void* d_out, int out_size) {
    const float* xyz    = (const float*)d_in[0];
    const float* feat   = (const float*)d_in[1];
    const float* bsize  = (const float*)d_in[2];
    const float* blabel = (const float*)d_in[3];
    const float* ts     = (const float*)d_in[4];
    const int*   inds   = (const int*)  d_in[5];
    const float* mw0 = (const float*)d_in[6],  *mb0 = (const float*)d_in[7];
    const float* mw1 = (const float*)d_in[8],  *mb1 = (const float*)d_in[9];
    const float* mw2 = (const float*)d_in[10], *mb2 = (const float*)d_in[11];
    const float* lw0 = (const float*)d_in[12], *lb0 = (const float*)d_in[13];
    const float* lw1 = (const float*)d_in[14], *lb1 = (const float*)d_in[15];
    const float* lw2 = (const float*)d_in[16], *lb2 = (const float*)d_in[17];
    const float* tw0 = (const float*)d_in[18], *tb0 = (const float*)d_in[19];
    const float* tw1 = (const float*)d_in[20], *tb1 = (const float*)d_in[21];
    const float* bw  = (const float*)d_in[22], *bbv = (const float*)d_in[23];
    const float* tlw0= (const float*)d_in[24], *tlb0= (const float*)d_in[25];
    const float* tlw1= (const float*)d_in[26], *tlb1= (const float*)d_in[27];
    const float* blw = (const float*)d_in[28], *blb = (const float*)d_in[29];
    float* out = (float*)d_out;

    dim3 tb(32, 8);
    k_prep<<<876, tb>>>(xyz, mw0, mw1, mw2, lw0, lw1, lw2);          // 0
    k_sample<<<BP, 128>>>(xyz, bsize, inds);                         // 1
    k_ftrans<<<dim3(625, 8, 8), tb>>>(feat);                         // 2

    int smem_b = (64*STR0 + 128*OS) * (int)sizeof(float);            // 102400 B
    cudaFuncSetAttribute(k_mlp, cudaFuncAttributeMaxDynamicSharedMemorySize, smem_b);
    k_mlp<<<BP/2, 256, smem_b>>>(xyz, inds, mb0, mb1, mb2,
                                 blabel, lb0, lb1, lb2);             // 3 <- profiled

    k_emb<<<BB, 128>>>(ts);                                          // 4
    int smem_t = (8*(1024+4) + 32*132) * (int)sizeof(float);         // 49792 B
    cudaFuncSetAttribute(k_tstage, cudaFuncAttributeMaxDynamicSharedMemorySize, smem_t);
    k_tstage<<<48, 256, smem_t>>>(tw0, tb0, tlw0, tlb0, 512, 0);     // 5
    k_tstage<<<48, 256, smem_t>>>(tw1, tb1, tlw1, tlb1, 512, 1);     // 6
    k_tstage<<<24, 256, smem_t>>>(bw,  bbv, blw,  blb,  256, 2);     // 7

    const int total = BB*PP*3 + BB*128*PP + BB*256*PP + BB*PP;       // 794624
    k_out<<<(total + 255)/256, 256>>>(out, xyz, inds);               // 8
}